// round 1
// baseline (speedup 1.0000x reference)
#include <cuda_runtime.h>

// ---------------- problem constants ----------------
#define NZ 9
#define ND 108          // depth cells (conv W dim)
#define NWC 124         // width cells (conv H dim)
#define NCELL 13392     // ND*NWC
#define NZN 120528      // NZ*NCELL
#define IMC_ 256
#define HC_ 2304        // 9*256
#define CATC 1280
#define OH1 62
#define OW1 54
#define OSP 3348        // 62*54

// ---------------- scratch (device globals; no allocs allowed) ----------------
__device__ __align__(16) float g_ii[7864320];                 // [H*W][256] channel-last integral image (max level0: 96*320*256)
__device__ __align__(16) float g_bbox[NZN * 4];               // normalized bboxes (same for all levels)
__device__ __align__(16) float g_vox[NCELL * HC_];            // [n][z*256+c] per level (reused)
__device__ __align__(16) float g_xcat[CATC * NCELL];          // concat ortho [1280][124][108] (unattended)
__device__ __align__(16) float g_wp[5 * IMC_ * HC_];          // permuted oft_w: [l][o][z*256+c]
__device__ __align__(16) float g_w1s[IMC_ * CATC * 9];        // conv1 weights scaled by attention s
__device__ float g_colmean[CATC];
__device__ float g_sig[CATC];
__device__ __align__(16) float g_y1[IMC_ * OSP];              // conv1 output

// ---------------- bbox projection ----------------
__device__ __forceinline__ float2 projnc(const float* __restrict__ P, int zi, int di, int wi) {
    float X = 0.64f * (float)di;
    float Y = 39.68f - 0.64f * (float)wi;   // 79.36 - 0.64*w - 39.68
    float Z = 2.76f - 0.64f * (float)zi;
    float hx = P[0] * X + P[1] * Y + P[2]  * Z + P[3];
    float hy = P[4] * X + P[5] * Y + P[6]  * Z + P[7];
    float hz = P[8] * X + P[9] * Y + P[10] * Z + P[11];
    float ix = hx / hz, iy = hy / hz;
    // img_size = [Wf,Hf]/scale = [1280, 384] for every level
    float nx = fminf(fmaxf(2.0f * ix / 1280.0f - 1.0f, -1.0f), 1.0f);
    float ny = fminf(fmaxf(2.0f * iy / 384.0f  - 1.0f, -1.0f), 1.0f);
    return make_float2(nx, ny);
}

__global__ void k_bbox(const float* __restrict__ P) {
    int idx = blockIdx.x * 256 + threadIdx.x;
    if (idx >= NZN) return;
    int z = idx / NCELL;
    int r = idx - z * NCELL;
    int d = r / NWC;
    int w = r - d * NWC;
    float2 a = projnc(P, z,     d,     w);
    float2 b = projnc(P, z,     d + 1, w);
    float2 c = projnc(P, z + 1, d + 1, w + 1);
    float2 e = projnc(P, z + 1, d,     w + 1);
    g_bbox[idx * 4 + 0] = fminf(a.x, b.x);
    g_bbox[idx * 4 + 1] = fminf(a.y, b.y);
    g_bbox[idx * 4 + 2] = fmaxf(c.x, e.x);
    g_bbox[idx * 4 + 3] = fmaxf(c.y, e.y);
}

// ---------------- integral image (channel-last) ----------------
__global__ void k_rowcum(const float* __restrict__ f, int H, int W) {
    int t = blockIdx.x * 256 + threadIdx.x;
    if (t >= 256 * H) return;
    int c = t & 255, h = t >> 8;
    const float* src = f + c * H * W + h * W;
    float* dst = g_ii + h * W * 256 + c;
    float a = 0.f;
    for (int w = 0; w < W; w++) { a += src[w]; dst[w * 256] = a; }
}

__global__ void k_colcum(int H, int W) {
    int t = blockIdx.x * 256 + threadIdx.x;
    if (t >= 256 * W) return;
    int c = t & 255, w = t >> 8;
    float* p = g_ii + w * 256 + c;
    float a = 0.f;
    for (int h = 0; h < H; h++) { int off = h * W * 256; a += p[off]; p[off] = a; }
}

// ---------------- voxel sampling: one block per (z,n), thread = channel ----------------
__global__ void k_vox(int Hf, int Wf, float areaF) {
    int idx = blockIdx.x;             // z*NCELL + n
    int z = idx / NCELL;
    int n = idx - z * NCELL;
    float4 bb = *(const float4*)&g_bbox[idx * 4];
    float x1 = bb.x, y1 = bb.y, x2 = bb.z, y2 = bb.w;
    float area = (x2 - x1) * (y2 - y1) * areaF + 1e-6f;
    bool vis = area > 1e-6f;

    float cx[4] = { x1, x2, x2, x1 };
    float cy[4] = { y1, y2, y1, y2 };
    float sg[4] = { 1.f, 1.f, -1.f, -1.f };   // +tl +br -tr -bl
    float cw[16];
    int   co[16];
#pragma unroll
    for (int i = 0; i < 4; i++) {
        float x = (cx[i] + 1.f) * (Wf * 0.5f) - 0.5f;
        float y = (cy[i] + 1.f) * (Hf * 0.5f) - 0.5f;
        float xf = floorf(x), yf = floorf(y);
        float wx = x - xf, wy = y - yf;
        int x0 = (int)xf, y0 = (int)yf;
#pragma unroll
        for (int j = 0; j < 4; j++) {
            int xi = x0 + (j & 1), yi = y0 + (j >> 1);
            bool ok = (xi >= 0 && xi < Wf && yi >= 0 && yi < Hf);
            float wt = ((j & 1) ? wx : 1.f - wx) * ((j >> 1) ? wy : 1.f - wy);
            co[i * 4 + j] = ok ? (yi * Wf + xi) * 256 : 0;
            cw[i * 4 + j] = ok ? sg[i] * wt : 0.f;
        }
    }
    int c = threadIdx.x;
    float v = 0.f;
#pragma unroll
    for (int j = 0; j < 16; j++) v += cw[j] * g_ii[co[j] + c];
    float out = vis ? (v / area) : 0.0f;
    g_vox[n * HC_ + z * 256 + c] = out;
}

// ---------------- permute oft_w to [l][o][z*256+c] ----------------
__global__ void k_permw(const float* __restrict__ w) {
    int idx = blockIdx.x * 256 + threadIdx.x;
    if (idx >= 5 * IMC_ * HC_) return;
    int k2 = idx % HC_;
    int lo = idx / HC_;            // l*256+o
    int z = k2 >> 8, c = k2 & 255;
    g_wp[idx] = w[lo * HC_ + c * NZ + z];
}

// ---------------- GEMM: out[n][o] = relu(vox[n,:]·wP[o,:] + b[o]) -> xcat[o][w][d] ----------------
__global__ __launch_bounds__(256) void k_gemm(int l, const float* __restrict__ bias) {
    const float* __restrict__ B = g_wp + l * IMC_ * HC_;
    float* __restrict__ Xc = g_xcat + l * IMC_ * NCELL;
    __shared__ float As[16][64];
    __shared__ float Bs[16][64];
    int tid = threadIdx.x;
    int tx = tid & 15, ty = tid >> 4;
    int ml = tid & 63, kq = tid >> 6;
    int n0 = blockIdx.x * 64, o0 = blockIdx.y * 64;

    float acc[4][4];
#pragma unroll
    for (int i = 0; i < 4; i++)
#pragma unroll
        for (int j = 0; j < 4; j++) acc[i][j] = 0.f;

    int arow = n0 + ml;
    bool avalid = arow < NCELL;
    const float4* Aro = (const float4*)(g_vox + (size_t)(avalid ? arow : 0) * HC_);
    const float4* Bro = (const float4*)(B + (size_t)(o0 + ml) * HC_);

    for (int k0 = 0; k0 < HC_; k0 += 16) {
        float4 av = avalid ? Aro[(k0 >> 2) + kq] : make_float4(0, 0, 0, 0);
        float4 bv = Bro[(k0 >> 2) + kq];
        As[kq * 4 + 0][ml] = av.x; As[kq * 4 + 1][ml] = av.y;
        As[kq * 4 + 2][ml] = av.z; As[kq * 4 + 3][ml] = av.w;
        Bs[kq * 4 + 0][ml] = bv.x; Bs[kq * 4 + 1][ml] = bv.y;
        Bs[kq * 4 + 2][ml] = bv.z; Bs[kq * 4 + 3][ml] = bv.w;
        __syncthreads();
#pragma unroll
        for (int k = 0; k < 16; k++) {
            float4 a4 = *(const float4*)&As[k][ty * 4];
            float4 b4 = *(const float4*)&Bs[k][tx * 4];
            float ar[4] = { a4.x, a4.y, a4.z, a4.w };
            float br[4] = { b4.x, b4.y, b4.z, b4.w };
#pragma unroll
            for (int i = 0; i < 4; i++)
#pragma unroll
                for (int j = 0; j < 4; j++) acc[i][j] += ar[i] * br[j];
        }
        __syncthreads();
    }
#pragma unroll
    for (int i = 0; i < 4; i++) {
        int n = n0 + ty * 4 + i;
        if (n >= NCELL) continue;
        int d = n / NWC, w = n - d * NWC;
        int sp = w * ND + d;
#pragma unroll
        for (int j = 0; j < 4; j++) {
            int o = o0 + tx * 4 + j;
            float v = acc[i][j] + bias[l * IMC_ + o];
            Xc[o * NCELL + sp] = fmaxf(v, 0.0f);
        }
    }
}

// ---------------- channel means over spatial (per concat channel) ----------------
__global__ void k_colmean() {
    int g = blockIdx.x;
    const float* p = g_xcat + g * NCELL;
    float s = 0.f;
    for (int i = threadIdx.x; i < NCELL; i += 256) s += p[i];
    __shared__ float sm[256];
    sm[threadIdx.x] = s;
    __syncthreads();
    for (int st = 128; st > 0; st >>= 1) {
        if (threadIdx.x < st) sm[threadIdx.x] += sm[threadIdx.x + st];
        __syncthreads();
    }
    if (threadIdx.x == 0) g_colmean[g] = sm[0] * (1.0f / (float)NCELL);
}

// ---------------- attention: s = sigmoid(mean @ aw.T + ab) per level ----------------
__global__ void k_att(const float* __restrict__ aw, const float* __restrict__ ab) {
    __shared__ float cm[IMC_];
    int l = blockIdx.x, o = threadIdx.x;
    cm[o] = g_colmean[l * IMC_ + o];
    __syncthreads();
    float acc = ab[o];
    for (int c = 0; c < IMC_; c++) acc += cm[c] * aw[o * IMC_ + c];
    g_sig[l * IMC_ + o] = 1.0f / (1.0f + expf(-acc));
}

// ---------------- fold attention into conv1 weights ----------------
__global__ void k_wscale(const float* __restrict__ w) {
    int idx = blockIdx.x * 256 + threadIdx.x;
    if (idx >= IMC_ * CATC * 9) return;
    int cin = (idx / 9) % CATC;
    g_w1s[idx] = w[idx] * g_sig[cin];
}

// ---------------- conv1: 3x3 stride2 pad1, 1280->256, + BN + ReLU ----------------
__global__ __launch_bounds__(128) void k_conv1(const float* __restrict__ bg, const float* __restrict__ bb,
                                               const float* __restrict__ bm, const float* __restrict__ bv) {
    int tid = threadIdx.x;
    int ob = blockIdx.y * 16;
    int p0 = blockIdx.x * 256 + tid;
    int p1 = p0 + 128;
    bool v0 = p0 < OSP, v1 = p1 < OSP;
    int q0 = v0 ? p0 : 0, q1 = v1 ? p1 : 0;
    int oh0 = q0 / OW1, ow0 = q0 - oh0 * OW1;
    int oh1 = q1 / OW1, ow1 = q1 - oh1 * OW1;

    float acc0[16], acc1[16];
#pragma unroll
    for (int t = 0; t < 16; t++) { acc0[t] = 0.f; acc1[t] = 0.f; }

    for (int cin = 0; cin < CATC; cin++) {
        const float* xc = g_xcat + cin * NCELL;   // [124][108]
        const float* wc = g_w1s + cin * 9;
#pragma unroll
        for (int ky = 0; ky < 3; ky++) {
            int ih0 = 2 * oh0 + ky - 1;
            int ih1 = 2 * oh1 + ky - 1;
#pragma unroll
            for (int kx = 0; kx < 3; kx++) {
                int iw0 = 2 * ow0 + kx - 1;
                int iw1 = 2 * ow1 + kx - 1;
                float x0 = (ih0 >= 0 && ih0 < NWC && iw0 >= 0 && iw0 < ND) ? xc[ih0 * ND + iw0] : 0.f;
                float x1 = (ih1 >= 0 && ih1 < NWC && iw1 >= 0 && iw1 < ND) ? xc[ih1 * ND + iw1] : 0.f;
#pragma unroll
                for (int t = 0; t < 16; t++) {
                    float wv = wc[(ob + t) * (CATC * 9) + ky * 3 + kx];
                    acc0[t] += x0 * wv;
                    acc1[t] += x1 * wv;
                }
            }
        }
    }
#pragma unroll
    for (int t = 0; t < 16; t++) {
        int o = ob + t;
        float sc = bg[o] / sqrtf(bv[o] + 1e-5f);
        if (v0) g_y1[o * OSP + p0] = fmaxf((acc0[t] - bm[o]) * sc + bb[o], 0.f);
        if (v1) g_y1[o * OSP + p1] = fmaxf((acc1[t] - bm[o]) * sc + bb[o], 0.f);
    }
}

// ---------------- conv2: 3x3 stride1 pad1, 256->256, + BN + ReLU -> d_out ----------------
__global__ __launch_bounds__(128) void k_conv2(const float* __restrict__ W2,
                                               const float* __restrict__ bg, const float* __restrict__ bb,
                                               const float* __restrict__ bm, const float* __restrict__ bv,
                                               float* __restrict__ out) {
    int tid = threadIdx.x;
    int ob = blockIdx.y * 16;
    int p0 = blockIdx.x * 256 + tid;
    int p1 = p0 + 128;
    bool v0 = p0 < OSP, v1 = p1 < OSP;
    int q0 = v0 ? p0 : 0, q1 = v1 ? p1 : 0;
    int oh0 = q0 / OW1, ow0 = q0 - oh0 * OW1;
    int oh1 = q1 / OW1, ow1 = q1 - oh1 * OW1;

    float acc0[16], acc1[16];
#pragma unroll
    for (int t = 0; t < 16; t++) { acc0[t] = 0.f; acc1[t] = 0.f; }

    for (int cin = 0; cin < IMC_; cin++) {
        const float* xc = g_y1 + cin * OSP;       // [62][54]
        const float* wc = W2 + cin * 9;
#pragma unroll
        for (int ky = 0; ky < 3; ky++) {
            int ih0 = oh0 + ky - 1;
            int ih1 = oh1 + ky - 1;
#pragma unroll
            for (int kx = 0; kx < 3; kx++) {
                int iw0 = ow0 + kx - 1;
                int iw1 = ow1 + kx - 1;
                float x0 = (ih0 >= 0 && ih0 < OH1 && iw0 >= 0 && iw0 < OW1) ? xc[ih0 * OW1 + iw0] : 0.f;
                float x1 = (ih1 >= 0 && ih1 < OH1 && iw1 >= 0 && iw1 < OW1) ? xc[ih1 * OW1 + iw1] : 0.f;
#pragma unroll
                for (int t = 0; t < 16; t++) {
                    float wv = wc[(ob + t) * (IMC_ * 9) + ky * 3 + kx];
                    acc0[t] += x0 * wv;
                    acc1[t] += x1 * wv;
                }
            }
        }
    }
#pragma unroll
    for (int t = 0; t < 16; t++) {
        int o = ob + t;
        float sc = bg[o] / sqrtf(bv[o] + 1e-5f);
        if (v0) out[o * OSP + p0] = fmaxf((acc0[t] - bm[o]) * sc + bb[o], 0.f);
        if (v1) out[o * OSP + p1] = fmaxf((acc1[t] - bm[o]) * sc + bb[o], 0.f);
    }
}

// ---------------- launch ----------------
extern "C" void kernel_launch(void* const* d_in, const int* in_sizes, int n_in,
                              void* d_out, int out_size) {
    (void)in_sizes; (void)n_in; (void)out_size;
    const float* feats[5] = {
        (const float*)d_in[0], (const float*)d_in[1], (const float*)d_in[2],
        (const float*)d_in[3], (const float*)d_in[4]
    };
    const float* calib = (const float*)d_in[5];
    const float* oftw  = (const float*)d_in[6];
    const float* oftb  = (const float*)d_in[7];
    const float* attw  = (const float*)d_in[8];
    const float* attb  = (const float*)d_in[9];
    const float* c1w   = (const float*)d_in[10];
    const float* b1g   = (const float*)d_in[11];
    const float* b1b   = (const float*)d_in[12];
    const float* b1m   = (const float*)d_in[13];
    const float* b1v   = (const float*)d_in[14];
    const float* c2w   = (const float*)d_in[15];
    const float* b2g   = (const float*)d_in[16];
    const float* b2b   = (const float*)d_in[17];
    const float* b2m   = (const float*)d_in[18];
    const float* b2v   = (const float*)d_in[19];
    float* out = (float*)d_out;

    k_bbox<<<(NZN + 255) / 256, 256>>>(calib);
    k_permw<<<(5 * IMC_ * HC_ + 255) / 256, 256>>>(oftw);

    static const int HH[5] = { 96, 48, 24, 12, 6 };
    static const int WW[5] = { 320, 160, 80, 40, 20 };
    for (int l = 0; l < 5; l++) {
        int H = HH[l], W = WW[l];
        k_rowcum<<<(256 * H + 255) / 256, 256>>>(feats[l], H, W);
        k_colcum<<<(256 * W + 255) / 256, 256>>>(H, W);
        k_vox<<<NZN, 256>>>(H, W, (float)(H * W) * 0.25f);
        k_gemm<<<dim3((NCELL + 63) / 64, 4), 256>>>(l, oftb);
    }
    k_colmean<<<CATC, 256>>>();
    k_att<<<5, 256>>>(attw, attb);
    k_wscale<<<(IMC_ * CATC * 9 + 255) / 256, 256>>>(c1w);
    k_conv1<<<dim3((OSP + 255) / 256, 16), 128>>>(b1g, b1b, b1m, b1v);
    k_conv2<<<dim3((OSP + 255) / 256, 16), 128>>>(c2w, b2g, b2b, b2m, b2v, out);
}

// round 2
// speedup vs baseline: 1.7942x; 1.7942x over previous
#include <cuda_runtime.h>

// ---------------- problem constants ----------------
#define NZ 9
#define ND 108          // depth cells (conv W dim)
#define NWC 124         // width cells (conv H dim)
#define NCELL 13392     // ND*NWC
#define NZN 120528      // NZ*NCELL
#define IMC_ 256
#define HC_ 2304        // 9*256
#define CATC 1280
#define OH1 62
#define OW1 54
#define OSP 3348        // 62*54

// ---------------- scratch (device globals; no allocs allowed) ----------------
__device__ __align__(16) float g_ii[7864320];                 // [H*W][256] channel-last integral image (max level0)
__device__ __align__(16) float g_bbox[NZN * 4];
__device__ __align__(16) float g_vox[NCELL * HC_];            // [n][z*256+c] per level (reused)
__device__ __align__(16) float g_xcat[CATC * NCELL];          // concat ortho [1280][124][108] (unattended)
__device__ __align__(16) float g_wp[5 * IMC_ * HC_];          // permuted oft_w: [l][o][z*256+c]
__device__ __align__(16) float g_w1s[CATC * 9 * IMC_];        // conv1 w: [cin][3][3][o] scaled by attention
__device__ __align__(16) float g_w2p[IMC_ * 9 * IMC_];        // conv2 w: [cin][3][3][o]
__device__ float g_colmean[CATC];
__device__ float g_sig[CATC];
__device__ __align__(16) float g_y1[IMC_ * OSP];              // conv1 output
__device__ __align__(16) float g_c1part[4 * IMC_ * OSP];
__device__ __align__(16) float g_c2part[2 * IMC_ * OSP];

// ---------------- bbox projection ----------------
__device__ __forceinline__ float2 projnc(const float* __restrict__ P, int zi, int di, int wi) {
    float X = 0.64f * (float)di;
    float Y = 39.68f - 0.64f * (float)wi;
    float Z = 2.76f - 0.64f * (float)zi;
    float hx = P[0] * X + P[1] * Y + P[2]  * Z + P[3];
    float hy = P[4] * X + P[5] * Y + P[6]  * Z + P[7];
    float hz = P[8] * X + P[9] * Y + P[10] * Z + P[11];
    float ix = hx / hz, iy = hy / hz;
    float nx = fminf(fmaxf(2.0f * ix / 1280.0f - 1.0f, -1.0f), 1.0f);
    float ny = fminf(fmaxf(2.0f * iy / 384.0f  - 1.0f, -1.0f), 1.0f);
    return make_float2(nx, ny);
}

__global__ void k_bbox(const float* __restrict__ P) {
    int idx = blockIdx.x * 256 + threadIdx.x;
    if (idx >= NZN) return;
    int z = idx / NCELL;
    int r = idx - z * NCELL;
    int d = r / NWC;
    int w = r - d * NWC;
    float2 a = projnc(P, z,     d,     w);
    float2 b = projnc(P, z,     d + 1, w);
    float2 c = projnc(P, z + 1, d + 1, w + 1);
    float2 e = projnc(P, z + 1, d,     w + 1);
    g_bbox[idx * 4 + 0] = fminf(a.x, b.x);
    g_bbox[idx * 4 + 1] = fminf(a.y, b.y);
    g_bbox[idx * 4 + 2] = fmaxf(c.x, e.x);
    g_bbox[idx * 4 + 3] = fmaxf(c.y, e.y);
}

// ---------------- integral image (channel-last) ----------------
__global__ void k_rowcum(const float* __restrict__ f, int H, int W) {
    int t = blockIdx.x * 256 + threadIdx.x;
    if (t >= 256 * H) return;
    int c = t & 255, h = t >> 8;
    const float* src = f + c * H * W + h * W;
    float* dst = g_ii + h * W * 256 + c;
    float a = 0.f;
    for (int w = 0; w < W; w++) { a += src[w]; dst[w * 256] = a; }
}

__global__ void k_colcum(int H, int W) {
    int t = blockIdx.x * 256 + threadIdx.x;
    if (t >= 256 * W) return;
    int c = t & 255, w = t >> 8;
    float* p = g_ii + w * 256 + c;
    float a = 0.f;
    for (int h = 0; h < H; h++) { int off = h * W * 256; a += p[off]; p[off] = a; }
}

// ---------------- voxel sampling ----------------
__global__ void k_vox(int Hf, int Wf, float areaF) {
    int idx = blockIdx.x;             // z*NCELL + n
    int z = idx / NCELL;
    int n = idx - z * NCELL;
    float4 bb = *(const float4*)&g_bbox[idx * 4];
    float x1 = bb.x, y1 = bb.y, x2 = bb.z, y2 = bb.w;
    float area = (x2 - x1) * (y2 - y1) * areaF + 1e-6f;
    bool vis = area > 1e-6f;

    float cx[4] = { x1, x2, x2, x1 };
    float cy[4] = { y1, y2, y1, y2 };
    float sg[4] = { 1.f, 1.f, -1.f, -1.f };
    float cw[16];
    int   co[16];
#pragma unroll
    for (int i = 0; i < 4; i++) {
        float x = (cx[i] + 1.f) * (Wf * 0.5f) - 0.5f;
        float y = (cy[i] + 1.f) * (Hf * 0.5f) - 0.5f;
        float xf = floorf(x), yf = floorf(y);
        float wx = x - xf, wy = y - yf;
        int x0 = (int)xf, y0 = (int)yf;
#pragma unroll
        for (int j = 0; j < 4; j++) {
            int xi = x0 + (j & 1), yi = y0 + (j >> 1);
            bool ok = (xi >= 0 && xi < Wf && yi >= 0 && yi < Hf);
            float wt = ((j & 1) ? wx : 1.f - wx) * ((j >> 1) ? wy : 1.f - wy);
            co[i * 4 + j] = ok ? (yi * Wf + xi) * 256 : 0;
            cw[i * 4 + j] = ok ? sg[i] * wt : 0.f;
        }
    }
    int c = threadIdx.x;
    float v = 0.f;
#pragma unroll
    for (int j = 0; j < 16; j++) v += cw[j] * g_ii[co[j] + c];
    float out = vis ? (v / area) : 0.0f;
    g_vox[n * HC_ + z * 256 + c] = out;
}

// ---------------- permute oft_w to [l][o][z*256+c] ----------------
__global__ void k_permw(const float* __restrict__ w) {
    int idx = blockIdx.x * 256 + threadIdx.x;
    if (idx >= 5 * IMC_ * HC_) return;
    int k2 = idx % HC_;
    int lo = idx / HC_;
    int z = k2 >> 8, c = k2 & 255;
    g_wp[idx] = w[lo * HC_ + c * NZ + z];
}

// ---------------- SGEMM 128x128x8, double-buffered, 8x8/thread ----------------
__global__ __launch_bounds__(256) void k_gemm(int l, const float* __restrict__ bias) {
    const float* __restrict__ A = g_vox;                  // [NCELL][2304]
    const float* __restrict__ B = g_wp + l * IMC_ * HC_;  // [256][2304]
    float* __restrict__ Xc = g_xcat + l * IMC_ * NCELL;

    __shared__ float As[2][8][128];
    __shared__ float Bs[2][8][128];

    int tid = threadIdx.x;
    int m0 = blockIdx.x * 128, o0 = blockIdx.y * 128;
    int lrow = tid >> 1, lcol = (tid & 1) * 4;
    int arow = m0 + lrow;
    bool av = arow < NCELL;
    const float* ag = A + (size_t)(av ? arow : 0) * HC_ + lcol;
    const float* bg = B + (size_t)(o0 + lrow) * HC_ + lcol;

    int tx = tid & 15, ty = tid >> 4;

    float acc[8][8];
#pragma unroll
    for (int i = 0; i < 8; i++)
#pragma unroll
        for (int j = 0; j < 8; j++) acc[i][j] = 0.f;

    // prologue: load tile 0
    {
        float4 a4 = av ? *(const float4*)ag : make_float4(0, 0, 0, 0);
        float4 b4 = *(const float4*)bg;
        As[0][lcol + 0][lrow] = a4.x; As[0][lcol + 1][lrow] = a4.y;
        As[0][lcol + 2][lrow] = a4.z; As[0][lcol + 3][lrow] = a4.w;
        Bs[0][lcol + 0][lrow] = b4.x; Bs[0][lcol + 1][lrow] = b4.y;
        Bs[0][lcol + 2][lrow] = b4.z; Bs[0][lcol + 3][lrow] = b4.w;
    }
    __syncthreads();

    const int nk = HC_ / 8;   // 288
    for (int kt = 0; kt < nk; kt++) {
        int buf = kt & 1;
        float4 an = make_float4(0, 0, 0, 0), bn = make_float4(0, 0, 0, 0);
        if (kt + 1 < nk) {
            if (av) an = *(const float4*)(ag + (kt + 1) * 8);
            bn = *(const float4*)(bg + (kt + 1) * 8);
        }
#pragma unroll
        for (int k = 0; k < 8; k++) {
            float4 a0 = *(const float4*)&As[buf][k][ty * 4];
            float4 a1 = *(const float4*)&As[buf][k][64 + ty * 4];
            float4 b0 = *(const float4*)&Bs[buf][k][tx * 4];
            float4 b1 = *(const float4*)&Bs[buf][k][64 + tx * 4];
            float ar[8] = { a0.x, a0.y, a0.z, a0.w, a1.x, a1.y, a1.z, a1.w };
            float br[8] = { b0.x, b0.y, b0.z, b0.w, b1.x, b1.y, b1.z, b1.w };
#pragma unroll
            for (int i = 0; i < 8; i++)
#pragma unroll
                for (int j = 0; j < 8; j++) acc[i][j] += ar[i] * br[j];
        }
        if (kt + 1 < nk) {
            int nb = buf ^ 1;
            As[nb][lcol + 0][lrow] = an.x; As[nb][lcol + 1][lrow] = an.y;
            As[nb][lcol + 2][lrow] = an.z; As[nb][lcol + 3][lrow] = an.w;
            Bs[nb][lcol + 0][lrow] = bn.x; Bs[nb][lcol + 1][lrow] = bn.y;
            Bs[nb][lcol + 2][lrow] = bn.z; Bs[nb][lcol + 3][lrow] = bn.w;
        }
        __syncthreads();
    }

#pragma unroll
    for (int i = 0; i < 8; i++) {
        int m = m0 + ((i < 4) ? (ty * 4 + i) : (64 + ty * 4 + i - 4));
        if (m >= NCELL) continue;
        int d = m / NWC, w = m - d * NWC;
        int sp = w * ND + d;
#pragma unroll
        for (int j = 0; j < 8; j++) {
            int o = o0 + ((j < 4) ? (tx * 4 + j) : (64 + tx * 4 + j - 4));
            float v = acc[i][j] + bias[l * IMC_ + o];
            Xc[o * NCELL + sp] = fmaxf(v, 0.0f);
        }
    }
}

// ---------------- channel means ----------------
__global__ void k_colmean() {
    int g = blockIdx.x;
    const float* p = g_xcat + g * NCELL;
    float s = 0.f;
    for (int i = threadIdx.x; i < NCELL; i += 256) s += p[i];
    __shared__ float sm[256];
    sm[threadIdx.x] = s;
    __syncthreads();
    for (int st = 128; st > 0; st >>= 1) {
        if (threadIdx.x < st) sm[threadIdx.x] += sm[threadIdx.x + st];
        __syncthreads();
    }
    if (threadIdx.x == 0) g_colmean[g] = sm[0] * (1.0f / (float)NCELL);
}

__global__ void k_att(const float* __restrict__ aw, const float* __restrict__ ab) {
    __shared__ float cm[IMC_];
    int l = blockIdx.x, o = threadIdx.x;
    cm[o] = g_colmean[l * IMC_ + o];
    __syncthreads();
    float acc = ab[o];
    for (int c = 0; c < IMC_; c++) acc += cm[c] * aw[o * IMC_ + c];
    g_sig[l * IMC_ + o] = 1.0f / (1.0f + expf(-acc));
}

// ---------------- fold attention + transpose conv1 weights: [cin][kk][o] ----------------
__global__ void k_wscale(const float* __restrict__ w) {
    int idx = blockIdx.x * 256 + threadIdx.x;
    if (idx >= CATC * 9 * IMC_) return;
    int o = idx & 255;
    int t = idx >> 8;
    int kk = t % 9;
    int cin = t / 9;
    g_w1s[idx] = w[(o * CATC + cin) * 9 + kk] * g_sig[cin];
}

// ---------------- transpose conv2 weights: [cin][kk][o] ----------------
__global__ void k_permw2(const float* __restrict__ w) {
    int idx = blockIdx.x * 256 + threadIdx.x;
    if (idx >= IMC_ * 9 * IMC_) return;
    int o = idx & 255;
    int t = idx >> 8;
    int kk = t % 9;
    int cin = t / 9;
    g_w2p[idx] = w[(o * IMC_ + cin) * 9 + kk];
}

// ---------------- conv1: 3x3 s2 p1, 1280->256, cin-split x4 partials ----------------
__global__ __launch_bounds__(256) void k_conv1() {
    int tid = threadIdx.x;
    int ob = blockIdx.y * 16;
    int c0 = blockIdx.z * 320;
    int p0 = blockIdx.x * 512 + tid;
    int p1 = p0 + 256;
    bool v0 = p0 < OSP, v1 = p1 < OSP;
    int q0 = v0 ? p0 : 0, q1 = v1 ? p1 : 0;
    int oh0 = q0 / OW1, ow0 = q0 - oh0 * OW1;
    int oh1 = q1 / OW1, ow1 = q1 - oh1 * OW1;

    float acc0[16], acc1[16];
#pragma unroll
    for (int t = 0; t < 16; t++) { acc0[t] = 0.f; acc1[t] = 0.f; }

    for (int cin = c0; cin < c0 + 320; cin++) {
        const float* xc = g_xcat + cin * NCELL;        // [124][108]
        const float* wrow = g_w1s + cin * 9 * 256 + ob;
#pragma unroll
        for (int ky = 0; ky < 3; ky++) {
            int ih0 = 2 * oh0 + ky - 1;
            int ih1 = 2 * oh1 + ky - 1;
#pragma unroll
            for (int kx = 0; kx < 3; kx++) {
                int iw0 = 2 * ow0 + kx - 1;
                int iw1 = 2 * ow1 + kx - 1;
                float x0 = (ih0 >= 0 && ih0 < NWC && iw0 >= 0 && iw0 < ND) ? xc[ih0 * ND + iw0] : 0.f;
                float x1 = (ih1 >= 0 && ih1 < NWC && iw1 >= 0 && iw1 < ND) ? xc[ih1 * ND + iw1] : 0.f;
                const float4* wv = (const float4*)(wrow + (ky * 3 + kx) * 256);
#pragma unroll
                for (int q = 0; q < 4; q++) {
                    float4 w4 = wv[q];
                    acc0[q * 4 + 0] += x0 * w4.x; acc1[q * 4 + 0] += x1 * w4.x;
                    acc0[q * 4 + 1] += x0 * w4.y; acc1[q * 4 + 1] += x1 * w4.y;
                    acc0[q * 4 + 2] += x0 * w4.z; acc1[q * 4 + 2] += x1 * w4.z;
                    acc0[q * 4 + 3] += x0 * w4.w; acc1[q * 4 + 3] += x1 * w4.w;
                }
            }
        }
    }
    float* part = g_c1part + blockIdx.z * IMC_ * OSP;
#pragma unroll
    for (int t = 0; t < 16; t++) {
        int o = ob + t;
        if (v0) part[o * OSP + p0] = acc0[t];
        if (v1) part[o * OSP + p1] = acc1[t];
    }
}

__global__ void k_c1red(const float* __restrict__ bg, const float* __restrict__ bb,
                        const float* __restrict__ bm, const float* __restrict__ bv) {
    int idx = blockIdx.x * 256 + threadIdx.x;
    if (idx >= IMC_ * OSP) return;
    int o = idx / OSP;
    float s = g_c1part[idx] + g_c1part[IMC_ * OSP + idx]
            + g_c1part[2 * IMC_ * OSP + idx] + g_c1part[3 * IMC_ * OSP + idx];
    float sc = bg[o] / sqrtf(bv[o] + 1e-5f);
    g_y1[idx] = fmaxf((s - bm[o]) * sc + bb[o], 0.f);
}

// ---------------- conv2: 3x3 s1 p1, 256->256, cin-split x2 partials ----------------
__global__ __launch_bounds__(256) void k_conv2() {
    int tid = threadIdx.x;
    int ob = blockIdx.y * 16;
    int c0 = blockIdx.z * 128;
    int p0 = blockIdx.x * 512 + tid;
    int p1 = p0 + 256;
    bool v0 = p0 < OSP, v1 = p1 < OSP;
    int q0 = v0 ? p0 : 0, q1 = v1 ? p1 : 0;
    int oh0 = q0 / OW1, ow0 = q0 - oh0 * OW1;
    int oh1 = q1 / OW1, ow1 = q1 - oh1 * OW1;

    float acc0[16], acc1[16];
#pragma unroll
    for (int t = 0; t < 16; t++) { acc0[t] = 0.f; acc1[t] = 0.f; }

    for (int cin = c0; cin < c0 + 128; cin++) {
        const float* xc = g_y1 + cin * OSP;            // [62][54]
        const float* wrow = g_w2p + cin * 9 * 256 + ob;
#pragma unroll
        for (int ky = 0; ky < 3; ky++) {
            int ih0 = oh0 + ky - 1;
            int ih1 = oh1 + ky - 1;
#pragma unroll
            for (int kx = 0; kx < 3; kx++) {
                int iw0 = ow0 + kx - 1;
                int iw1 = ow1 + kx - 1;
                float x0 = (ih0 >= 0 && ih0 < OH1 && iw0 >= 0 && iw0 < OW1) ? xc[ih0 * OW1 + iw0] : 0.f;
                float x1 = (ih1 >= 0 && ih1 < OH1 && iw1 >= 0 && iw1 < OW1) ? xc[ih1 * OW1 + iw1] : 0.f;
                const float4* wv = (const float4*)(wrow + (ky * 3 + kx) * 256);
#pragma unroll
                for (int q = 0; q < 4; q++) {
                    float4 w4 = wv[q];
                    acc0[q * 4 + 0] += x0 * w4.x; acc1[q * 4 + 0] += x1 * w4.x;
                    acc0[q * 4 + 1] += x0 * w4.y; acc1[q * 4 + 1] += x1 * w4.y;
                    acc0[q * 4 + 2] += x0 * w4.z; acc1[q * 4 + 2] += x1 * w4.z;
                    acc0[q * 4 + 3] += x0 * w4.w; acc1[q * 4 + 3] += x1 * w4.w;
                }
            }
        }
    }
    float* part = g_c2part + blockIdx.z * IMC_ * OSP;
#pragma unroll
    for (int t = 0; t < 16; t++) {
        int o = ob + t;
        if (v0) part[o * OSP + p0] = acc0[t];
        if (v1) part[o * OSP + p1] = acc1[t];
    }
}

__global__ void k_c2red(const float* __restrict__ bg, const float* __restrict__ bb,
                        const float* __restrict__ bm, const float* __restrict__ bv,
                        float* __restrict__ out) {
    int idx = blockIdx.x * 256 + threadIdx.x;
    if (idx >= IMC_ * OSP) return;
    int o = idx / OSP;
    float s = g_c2part[idx] + g_c2part[IMC_ * OSP + idx];
    float sc = bg[o] / sqrtf(bv[o] + 1e-5f);
    out[idx] = fmaxf((s - bm[o]) * sc + bb[o], 0.f);
}

// ---------------- launch ----------------
extern "C" void kernel_launch(void* const* d_in, const int* in_sizes, int n_in,
                              void* d_out, int out_size) {
    (void)in_sizes; (void)n_in; (void)out_size;
    const float* feats[5] = {
        (const float*)d_in[0], (const float*)d_in[1], (const float*)d_in[2],
        (const float*)d_in[3], (const float*)d_in[4]
    };
    const float* calib = (const float*)d_in[5];
    const float* oftw  = (const float*)d_in[6];
    const float* oftb  = (const float*)d_in[7];
    const float* attw  = (const float*)d_in[8];
    const float* attb  = (const float*)d_in[9];
    const float* c1w   = (const float*)d_in[10];
    const float* b1g   = (const float*)d_in[11];
    const float* b1b   = (const float*)d_in[12];
    const float* b1m   = (const float*)d_in[13];
    const float* b1v   = (const float*)d_in[14];
    const float* c2w   = (const float*)d_in[15];
    const float* b2g   = (const float*)d_in[16];
    const float* b2b   = (const float*)d_in[17];
    const float* b2m   = (const float*)d_in[18];
    const float* b2v   = (const float*)d_in[19];
    float* out = (float*)d_out;

    k_bbox<<<(NZN + 255) / 256, 256>>>(calib);
    k_permw<<<(5 * IMC_ * HC_ + 255) / 256, 256>>>(oftw);
    k_permw2<<<(IMC_ * 9 * IMC_ + 255) / 256, 256>>>(c2w);

    static const int HH[5] = { 96, 48, 24, 12, 6 };
    static const int WW[5] = { 320, 160, 80, 40, 20 };
    for (int l = 0; l < 5; l++) {
        int H = HH[l], W = WW[l];
        k_rowcum<<<(256 * H + 255) / 256, 256>>>(feats[l], H, W);
        k_colcum<<<(256 * W + 255) / 256, 256>>>(H, W);
        k_vox<<<NZN, 256>>>(H, W, (float)(H * W) * 0.25f);
        k_gemm<<<dim3((NCELL + 127) / 128, 2), 256>>>(l, oftb);
    }
    k_colmean<<<CATC, 256>>>();
    k_att<<<5, 256>>>(attw, attb);
    k_wscale<<<(CATC * 9 * IMC_ + 255) / 256, 256>>>(c1w);
    k_conv1<<<dim3(7, 16, 4), 256>>>();
    k_c1red<<<(IMC_ * OSP + 255) / 256, 256>>>(b1g, b1b, b1m, b1v);
    k_conv2<<<dim3(7, 16, 2), 256>>>();
    k_c2red<<<(IMC_ * OSP + 255) / 256, 256>>>(b2g, b2b, b2m, b2v, out);
}

// round 3
// speedup vs baseline: 2.8830x; 1.6068x over previous
#include <cuda_runtime.h>

// ---------------- problem constants ----------------
#define NZ 9
#define ND 108          // depth cells (conv W dim)
#define NWC 124         // width cells (conv H dim)
#define NCELL 13392     // ND*NWC
#define NZN 120528      // NZ*NCELL
#define IMC_ 256
#define HC_ 2304        // 9*256
#define CATC 1280
#define OH1 62
#define OW1 54
#define OSP 3348        // 62*54

// level geometry
__device__ __constant__ int c_HH[5] = { 96, 48, 24, 12, 6 };
__device__ __constant__ int c_WW[5] = { 320, 160, 80, 40, 20 };
// float-offsets of per-level channel-last buffers (HW*256)
__device__ __constant__ int c_IIOFF[5] = { 0, 7864320, 9830400, 10321920, 10444800 };
// float-offsets of per-level P buffers (HW*2304)
__device__ __constant__ int c_POFF[5]  = { 0, 70778880, 88473600, 92897280, 94003200 };
// cumulative M-tile (128) counts per level for the fused GEMM
__device__ __constant__ int c_MTCUM[6] = { 0, 240, 300, 315, 319, 320 };

// ---------------- scratch (device globals; no allocs allowed) ----------------
__device__ __align__(16) float g_ii[10475520];      // all 5 levels, [hw][256] channel-last
__device__ __align__(16) float g_P[94279680];       // all 5 levels, [z][hw][256] projected integral
__device__ __align__(16) float g_bbox[NZN * 4];
__device__ __align__(16) float g_wb[5 * HC_ * IMC_];  // [l][z*256+o][c] weights for P-GEMM
__device__ __align__(16) float g_xcat[CATC * NCELL];  // concat ortho [1280][124][108]
__device__ __align__(16) float g_w1s[CATC * 9 * IMC_];
__device__ __align__(16) float g_w2p[IMC_ * 9 * IMC_];
__device__ float g_colmean[CATC];
__device__ float g_sig[CATC];
__device__ __align__(16) float g_y1[IMC_ * OSP];
__device__ __align__(16) float g_c1part[4 * IMC_ * OSP];
__device__ __align__(16) float g_c2part[2 * IMC_ * OSP];

// ---------------- bbox projection ----------------
__device__ __forceinline__ float2 projnc(const float* __restrict__ P, int zi, int di, int wi) {
    float X = 0.64f * (float)di;
    float Y = 39.68f - 0.64f * (float)wi;
    float Z = 2.76f - 0.64f * (float)zi;
    float hx = P[0] * X + P[1] * Y + P[2]  * Z + P[3];
    float hy = P[4] * X + P[5] * Y + P[6]  * Z + P[7];
    float hz = P[8] * X + P[9] * Y + P[10] * Z + P[11];
    float ix = hx / hz, iy = hy / hz;
    float nx = fminf(fmaxf(2.0f * ix / 1280.0f - 1.0f, -1.0f), 1.0f);
    float ny = fminf(fmaxf(2.0f * iy / 384.0f  - 1.0f, -1.0f), 1.0f);
    return make_float2(nx, ny);
}

__global__ void k_bbox(const float* __restrict__ P) {
    int idx = blockIdx.x * 256 + threadIdx.x;
    if (idx >= NZN) return;
    int z = idx / NCELL;
    int r = idx - z * NCELL;
    int d = r / NWC;
    int w = r - d * NWC;
    float2 a = projnc(P, z,     d,     w);
    float2 b = projnc(P, z,     d + 1, w);
    float2 c = projnc(P, z + 1, d + 1, w + 1);
    float2 e = projnc(P, z + 1, d,     w + 1);
    g_bbox[idx * 4 + 0] = fminf(a.x, b.x);
    g_bbox[idx * 4 + 1] = fminf(a.y, b.y);
    g_bbox[idx * 4 + 2] = fmaxf(c.x, e.x);
    g_bbox[idx * 4 + 3] = fmaxf(c.y, e.y);
}

// ---------------- transpose feats [256][HW] -> channel-last [hw][256] ----------------
__global__ void k_trans(const float* __restrict__ f, int l, int HW) {
    __shared__ float t[32][33];
    int hw0 = blockIdx.x * 32, c0 = blockIdx.y * 32;
    int tx = threadIdx.x, ty = threadIdx.y;
    int hw = hw0 + tx;
    if (hw < HW) t[ty][tx] = f[(c0 + ty) * HW + hw];
    __syncthreads();
    int hww = hw0 + ty;
    if (hww < HW) g_ii[c_IIOFF[l] + hww * 256 + c0 + tx] = t[tx][ty];
}

// ---------------- cumsum along w (channel-last, coalesced) ----------------
__global__ void k_rowcum(int l, int H, int W) {
    int t = blockIdx.x * 256 + threadIdx.x;
    if (t >= 256 * H) return;
    int c = t & 255, h = t >> 8;
    float* p = g_ii + c_IIOFF[l] + h * W * 256 + c;
    float a = 0.f;
    for (int w = 0; w < W; w++) { int off = w * 256; a += p[off]; p[off] = a; }
}

// ---------------- cumsum along h ----------------
__global__ void k_colcum(int l, int H, int W) {
    int t = blockIdx.x * 256 + threadIdx.x;
    if (t >= 256 * W) return;
    int c = t & 255, w = t >> 8;
    float* p = g_ii + c_IIOFF[l] + w * 256 + c;
    float a = 0.f;
    for (int h = 0; h < H; h++) { int off = h * W * 256; a += p[off]; p[off] = a; }
}

// ---------------- permute oft_w: g_wb[l][z*256+o][c] = w[l][o][c*9+z] ----------------
__global__ void k_permwb(const float* __restrict__ w) {
    int idx = blockIdx.x * 256 + threadIdx.x;
    if (idx >= 5 * HC_ * IMC_) return;
    int c = idx & 255;
    int t = idx >> 8;
    int zo = t % HC_;
    int l = t / HC_;
    int z = zo >> 8, o = zo & 255;
    g_wb[idx] = w[(l * IMC_ + o) * HC_ + c * 9 + z];
}

// ---------------- fused P-GEMM over all levels: P[z][hw][o] = ii[hw][:]·Wz[o][:] ----------------
__global__ __launch_bounds__(256) void k_pgemm() {
    // find level from blockIdx.x
    int bx = blockIdx.x;
    int l = 0;
    while (bx >= c_MTCUM[l + 1]) l++;
    int mtile = bx - c_MTCUM[l];
    int HW = c_HH[l] * c_WW[l];
    const float* __restrict__ A = g_ii + c_IIOFF[l];          // [HW][256]
    const float* __restrict__ B = g_wb + l * HC_ * IMC_;      // [2304][256]
    float* __restrict__ P = g_P + c_POFF[l];

    __shared__ float As[2][8][128];
    __shared__ float Bs[2][8][128];

    int tid = threadIdx.x;
    int m0 = mtile * 128, o0 = blockIdx.y * 128;
    int lrow = tid >> 1, lcol = (tid & 1) * 4;
    int arow = m0 + lrow;
    bool av = arow < HW;
    const float* ag = A + (size_t)(av ? arow : 0) * 256 + lcol;
    const float* bg = B + (size_t)(o0 + lrow) * 256 + lcol;

    int tx = tid & 15, ty = tid >> 4;

    float acc[8][8];
#pragma unroll
    for (int i = 0; i < 8; i++)
#pragma unroll
        for (int j = 0; j < 8; j++) acc[i][j] = 0.f;

    {
        float4 a4 = av ? *(const float4*)ag : make_float4(0, 0, 0, 0);
        float4 b4 = *(const float4*)bg;
        As[0][lcol + 0][lrow] = a4.x; As[0][lcol + 1][lrow] = a4.y;
        As[0][lcol + 2][lrow] = a4.z; As[0][lcol + 3][lrow] = a4.w;
        Bs[0][lcol + 0][lrow] = b4.x; Bs[0][lcol + 1][lrow] = b4.y;
        Bs[0][lcol + 2][lrow] = b4.z; Bs[0][lcol + 3][lrow] = b4.w;
    }
    __syncthreads();

    const int nk = 256 / 8;   // 32
    for (int kt = 0; kt < nk; kt++) {
        int buf = kt & 1;
        float4 an = make_float4(0, 0, 0, 0), bn = make_float4(0, 0, 0, 0);
        if (kt + 1 < nk) {
            if (av) an = *(const float4*)(ag + (kt + 1) * 8);
            bn = *(const float4*)(bg + (kt + 1) * 8);
        }
#pragma unroll
        for (int k = 0; k < 8; k++) {
            float4 a0 = *(const float4*)&As[buf][k][ty * 4];
            float4 a1 = *(const float4*)&As[buf][k][64 + ty * 4];
            float4 b0 = *(const float4*)&Bs[buf][k][tx * 4];
            float4 b1 = *(const float4*)&Bs[buf][k][64 + tx * 4];
            float ar[8] = { a0.x, a0.y, a0.z, a0.w, a1.x, a1.y, a1.z, a1.w };
            float br[8] = { b0.x, b0.y, b0.z, b0.w, b1.x, b1.y, b1.z, b1.w };
#pragma unroll
            for (int i = 0; i < 8; i++)
#pragma unroll
                for (int j = 0; j < 8; j++) acc[i][j] += ar[i] * br[j];
        }
        if (kt + 1 < nk) {
            int nb = buf ^ 1;
            As[nb][lcol + 0][lrow] = an.x; As[nb][lcol + 1][lrow] = an.y;
            As[nb][lcol + 2][lrow] = an.z; As[nb][lcol + 3][lrow] = an.w;
            Bs[nb][lcol + 0][lrow] = bn.x; Bs[nb][lcol + 1][lrow] = bn.y;
            Bs[nb][lcol + 2][lrow] = bn.z; Bs[nb][lcol + 3][lrow] = bn.w;
        }
        __syncthreads();
    }

    // n-range [o0, o0+128) lies inside one z (256 = two 128-tiles per z)
    int z = o0 >> 8;
    int ob = o0 & 255;
#pragma unroll
    for (int i = 0; i < 8; i++) {
        int m = m0 + ((i < 4) ? (ty * 4 + i) : (64 + ty * 4 + i - 4));
        if (m >= HW) continue;
        float* dst = P + ((size_t)z * HW + m) * 256 + ob + tx * 4;
        float4 v0 = make_float4(acc[i][0], acc[i][1], acc[i][2], acc[i][3]);
        float4 v1 = make_float4(acc[i][4], acc[i][5], acc[i][6], acc[i][7]);
        *(float4*)dst = v0;
        *(float4*)(dst + 64) = v1;
    }
}

// ---------------- fused gather: ortho[n][o] = relu(b + sum_z sum_taps w*P) ----------------
__global__ __launch_bounds__(256) void k_gather(const float* __restrict__ bias) {
    int n = blockIdx.x;
    int l = blockIdx.y;
    int o = threadIdx.x;
    int Hf = c_HH[l], Wf = c_WW[l];
    int HW = Hf * Wf;
    float areaF = (float)(Hf * Wf) * 0.25f;
    const float* __restrict__ P = g_P + c_POFF[l];

    float acc = bias[l * 256 + o];

    for (int z = 0; z < NZ; z++) {
        float4 bb = *(const float4*)&g_bbox[(z * NCELL + n) * 4];
        float area = (bb.z - bb.x) * (bb.w - bb.y) * areaF + 1e-6f;
        if (!(area > 1e-6f)) continue;
        float inv = 1.0f / area;

        // separable weights: cols from {x1,x2}, rows from {y1,y2}; x2/y2 negated
        float cwv[4]; int coff[4];
        {
            float xs[2] = { bb.x, bb.z };
#pragma unroll
            for (int s = 0; s < 2; s++) {
                float x = (xs[s] + 1.f) * (Wf * 0.5f) - 0.5f;
                float xf = floorf(x);
                float wx = x - xf;
                int xi = (int)xf;
                float sg = s ? -1.f : 1.f;
                bool ok0 = (xi >= 0) && (xi < Wf);
                bool ok1 = (xi + 1 >= 0) && (xi + 1 < Wf);
                cwv[s * 2 + 0] = ok0 ? sg * (1.f - wx) : 0.f;
                cwv[s * 2 + 1] = ok1 ? sg * wx : 0.f;
                coff[s * 2 + 0] = ok0 ? xi * 256 : 0;
                coff[s * 2 + 1] = ok1 ? (xi + 1) * 256 : 0;
            }
        }
        float rwv[4]; int roff[4];
        {
            float ys[2] = { bb.y, bb.w };
#pragma unroll
            for (int s = 0; s < 2; s++) {
                float y = (ys[s] + 1.f) * (Hf * 0.5f) - 0.5f;
                float yf = floorf(y);
                float wy = y - yf;
                int yi = (int)yf;
                float sg = s ? -1.f : 1.f;
                bool ok0 = (yi >= 0) && (yi < Hf);
                bool ok1 = (yi + 1 >= 0) && (yi + 1 < Hf);
                rwv[s * 2 + 0] = ok0 ? sg * (1.f - wy) * inv : 0.f;
                rwv[s * 2 + 1] = ok1 ? sg * wy * inv : 0.f;
                roff[s * 2 + 0] = ok0 ? yi * Wf * 256 : 0;
                roff[s * 2 + 1] = ok1 ? (yi + 1) * Wf * 256 : 0;
            }
        }
        const float* Pz = P + (size_t)z * HW * 256 + o;
#pragma unroll
        for (int j = 0; j < 4; j++) {
            const float* Pr = Pz + roff[j];
            float rs = cwv[0] * Pr[coff[0]] + cwv[1] * Pr[coff[1]]
                     + cwv[2] * Pr[coff[2]] + cwv[3] * Pr[coff[3]];
            acc += rwv[j] * rs;
        }
    }
    int d = n / NWC, w = n - d * NWC;
    int sp = w * ND + d;
    g_xcat[(l * 256 + o) * NCELL + sp] = fmaxf(acc, 0.0f);
}

// ---------------- channel means ----------------
__global__ void k_colmean() {
    int g = blockIdx.x;
    const float* p = g_xcat + g * NCELL;
    float s = 0.f;
    for (int i = threadIdx.x; i < NCELL; i += 256) s += p[i];
    __shared__ float sm[256];
    sm[threadIdx.x] = s;
    __syncthreads();
    for (int st = 128; st > 0; st >>= 1) {
        if (threadIdx.x < st) sm[threadIdx.x] += sm[threadIdx.x + st];
        __syncthreads();
    }
    if (threadIdx.x == 0) g_colmean[g] = sm[0] * (1.0f / (float)NCELL);
}

__global__ void k_att(const float* __restrict__ aw, const float* __restrict__ ab) {
    __shared__ float cm[IMC_];
    int l = blockIdx.x, o = threadIdx.x;
    cm[o] = g_colmean[l * IMC_ + o];
    __syncthreads();
    float acc = ab[o];
    for (int c = 0; c < IMC_; c++) acc += cm[c] * aw[o * IMC_ + c];
    g_sig[l * IMC_ + o] = 1.0f / (1.0f + expf(-acc));
}

// ---------------- fold attention + transpose conv1 weights: [cin][kk][o] ----------------
__global__ void k_wscale(const float* __restrict__ w) {
    int idx = blockIdx.x * 256 + threadIdx.x;
    if (idx >= CATC * 9 * IMC_) return;
    int o = idx & 255;
    int t = idx >> 8;
    int kk = t % 9;
    int cin = t / 9;
    g_w1s[idx] = w[(o * CATC + cin) * 9 + kk] * g_sig[cin];
}

__global__ void k_permw2(const float* __restrict__ w) {
    int idx = blockIdx.x * 256 + threadIdx.x;
    if (idx >= IMC_ * 9 * IMC_) return;
    int o = idx & 255;
    int t = idx >> 8;
    int kk = t % 9;
    int cin = t / 9;
    g_w2p[idx] = w[(o * IMC_ + cin) * 9 + kk];
}

// ---------------- conv1: 3x3 s2 p1, 1280->256, cin-split x4 partials ----------------
__global__ __launch_bounds__(256) void k_conv1() {
    int tid = threadIdx.x;
    int ob = blockIdx.y * 16;
    int c0 = blockIdx.z * 320;
    int p0 = blockIdx.x * 512 + tid;
    int p1 = p0 + 256;
    bool v0 = p0 < OSP, v1 = p1 < OSP;
    int q0 = v0 ? p0 : 0, q1 = v1 ? p1 : 0;
    int oh0 = q0 / OW1, ow0 = q0 - oh0 * OW1;
    int oh1 = q1 / OW1, ow1 = q1 - oh1 * OW1;

    float acc0[16], acc1[16];
#pragma unroll
    for (int t = 0; t < 16; t++) { acc0[t] = 0.f; acc1[t] = 0.f; }

    for (int cin = c0; cin < c0 + 320; cin++) {
        const float* xc = g_xcat + cin * NCELL;
        const float* wrow = g_w1s + cin * 9 * 256 + ob;
#pragma unroll
        for (int ky = 0; ky < 3; ky++) {
            int ih0 = 2 * oh0 + ky - 1;
            int ih1 = 2 * oh1 + ky - 1;
#pragma unroll
            for (int kx = 0; kx < 3; kx++) {
                int iw0 = 2 * ow0 + kx - 1;
                int iw1 = 2 * ow1 + kx - 1;
                float x0 = (ih0 >= 0 && ih0 < NWC && iw0 >= 0 && iw0 < ND) ? xc[ih0 * ND + iw0] : 0.f;
                float x1 = (ih1 >= 0 && ih1 < NWC && iw1 >= 0 && iw1 < ND) ? xc[ih1 * ND + iw1] : 0.f;
                const float4* wv = (const float4*)(wrow + (ky * 3 + kx) * 256);
#pragma unroll
                for (int q = 0; q < 4; q++) {
                    float4 w4 = wv[q];
                    acc0[q * 4 + 0] += x0 * w4.x; acc1[q * 4 + 0] += x1 * w4.x;
                    acc0[q * 4 + 1] += x0 * w4.y; acc1[q * 4 + 1] += x1 * w4.y;
                    acc0[q * 4 + 2] += x0 * w4.z; acc1[q * 4 + 2] += x1 * w4.z;
                    acc0[q * 4 + 3] += x0 * w4.w; acc1[q * 4 + 3] += x1 * w4.w;
                }
            }
        }
    }
    float* part = g_c1part + blockIdx.z * IMC_ * OSP;
#pragma unroll
    for (int t = 0; t < 16; t++) {
        int o = ob + t;
        if (v0) part[o * OSP + p0] = acc0[t];
        if (v1) part[o * OSP + p1] = acc1[t];
    }
}

__global__ void k_c1red(const float* __restrict__ bg, const float* __restrict__ bb,
                        const float* __restrict__ bm, const float* __restrict__ bv) {
    int idx = blockIdx.x * 256 + threadIdx.x;
    if (idx >= IMC_ * OSP) return;
    int o = idx / OSP;
    float s = g_c1part[idx] + g_c1part[IMC_ * OSP + idx]
            + g_c1part[2 * IMC_ * OSP + idx] + g_c1part[3 * IMC_ * OSP + idx];
    float sc = bg[o] / sqrtf(bv[o] + 1e-5f);
    g_y1[idx] = fmaxf((s - bm[o]) * sc + bb[o], 0.f);
}

// ---------------- conv2: 3x3 s1 p1, 256->256, cin-split x2 partials ----------------
__global__ __launch_bounds__(256) void k_conv2() {
    int tid = threadIdx.x;
    int ob = blockIdx.y * 16;
    int c0 = blockIdx.z * 128;
    int p0 = blockIdx.x * 512 + tid;
    int p1 = p0 + 256;
    bool v0 = p0 < OSP, v1 = p1 < OSP;
    int q0 = v0 ? p0 : 0, q1 = v1 ? p1 : 0;
    int oh0 = q0 / OW1, ow0 = q0 - oh0 * OW1;
    int oh1 = q1 / OW1, ow1 = q1 - oh1 * OW1;

    float acc0[16], acc1[16];
#pragma unroll
    for (int t = 0; t < 16; t++) { acc0[t] = 0.f; acc1[t] = 0.f; }

    for (int cin = c0; cin < c0 + 128; cin++) {
        const float* xc = g_y1 + cin * OSP;
        const float* wrow = g_w2p + cin * 9 * 256 + ob;
#pragma unroll
        for (int ky = 0; ky < 3; ky++) {
            int ih0 = oh0 + ky - 1;
            int ih1 = oh1 + ky - 1;
#pragma unroll
            for (int kx = 0; kx < 3; kx++) {
                int iw0 = ow0 + kx - 1;
                int iw1 = ow1 + kx - 1;
                float x0 = (ih0 >= 0 && ih0 < OH1 && iw0 >= 0 && iw0 < OW1) ? xc[ih0 * OW1 + iw0] : 0.f;
                float x1 = (ih1 >= 0 && ih1 < OH1 && iw1 >= 0 && iw1 < OW1) ? xc[ih1 * OW1 + iw1] : 0.f;
                const float4* wv = (const float4*)(wrow + (ky * 3 + kx) * 256);
#pragma unroll
                for (int q = 0; q < 4; q++) {
                    float4 w4 = wv[q];
                    acc0[q * 4 + 0] += x0 * w4.x; acc1[q * 4 + 0] += x1 * w4.x;
                    acc0[q * 4 + 1] += x0 * w4.y; acc1[q * 4 + 1] += x1 * w4.y;
                    acc0[q * 4 + 2] += x0 * w4.z; acc1[q * 4 + 2] += x1 * w4.z;
                    acc0[q * 4 + 3] += x0 * w4.w; acc1[q * 4 + 3] += x1 * w4.w;
                }
            }
        }
    }
    float* part = g_c2part + blockIdx.z * IMC_ * OSP;
#pragma unroll
    for (int t = 0; t < 16; t++) {
        int o = ob + t;
        if (v0) part[o * OSP + p0] = acc0[t];
        if (v1) part[o * OSP + p1] = acc1[t];
    }
}

__global__ void k_c2red(const float* __restrict__ bg, const float* __restrict__ bb,
                        const float* __restrict__ bm, const float* __restrict__ bv,
                        float* __restrict__ out) {
    int idx = blockIdx.x * 256 + threadIdx.x;
    if (idx >= IMC_ * OSP) return;
    int o = idx / OSP;
    float s = g_c2part[idx] + g_c2part[IMC_ * OSP + idx];
    float sc = bg[o] / sqrtf(bv[o] + 1e-5f);
    out[idx] = fmaxf((s - bm[o]) * sc + bb[o], 0.f);
}

// ---------------- launch ----------------
extern "C" void kernel_launch(void* const* d_in, const int* in_sizes, int n_in,
                              void* d_out, int out_size) {
    (void)in_sizes; (void)n_in; (void)out_size;
    const float* feats[5] = {
        (const float*)d_in[0], (const float*)d_in[1], (const float*)d_in[2],
        (const float*)d_in[3], (const float*)d_in[4]
    };
    const float* calib = (const float*)d_in[5];
    const float* oftw  = (const float*)d_in[6];
    const float* oftb  = (const float*)d_in[7];
    const float* attw  = (const float*)d_in[8];
    const float* attb  = (const float*)d_in[9];
    const float* c1w   = (const float*)d_in[10];
    const float* b1g   = (const float*)d_in[11];
    const float* b1b   = (const float*)d_in[12];
    const float* b1m   = (const float*)d_in[13];
    const float* b1v   = (const float*)d_in[14];
    const float* c2w   = (const float*)d_in[15];
    const float* b2g   = (const float*)d_in[16];
    const float* b2b   = (const float*)d_in[17];
    const float* b2m   = (const float*)d_in[18];
    const float* b2v   = (const float*)d_in[19];
    float* out = (float*)d_out;

    k_bbox<<<(NZN + 255) / 256, 256>>>(calib);
    k_permwb<<<(5 * HC_ * IMC_ + 255) / 256, 256>>>(oftw);
    k_permw2<<<(IMC_ * 9 * IMC_ + 255) / 256, 256>>>(c2w);

    static const int HH[5] = { 96, 48, 24, 12, 6 };
    static const int WW[5] = { 320, 160, 80, 40, 20 };
    for (int l = 0; l < 5; l++) {
        int H = HH[l], W = WW[l];
        int HW = H * W;
        dim3 tb(32, 32);
        k_trans<<<dim3((HW + 31) / 32, 8), tb>>>(feats[l], l, HW);
        k_rowcum<<<(256 * H + 255) / 256, 256>>>(l, H, W);
        k_colcum<<<(256 * W + 255) / 256, 256>>>(l, H, W);
    }
    k_pgemm<<<dim3(320, 18), 256>>>();
    k_gather<<<dim3(NCELL, 5), 256>>>(oftb);

    k_colmean<<<CATC, 256>>>();
    k_att<<<5, 256>>>(attw, attb);
    k_wscale<<<(CATC * 9 * IMC_ + 255) / 256, 256>>>(c1w);
    k_conv1<<<dim3(7, 16, 4), 256>>>();
    k_c1red<<<(IMC_ * OSP + 255) / 256, 256>>>(b1g, b1b, b1m, b1v);
    k_conv2<<<dim3(7, 16, 2), 256>>>();
    k_c2red<<<(IMC_ * OSP + 255) / 256, 256>>>(b2g, b2b, b2m, b2v, out);
}

// round 4
// speedup vs baseline: 3.3017x; 1.1452x over previous
#include <cuda_runtime.h>
#include <cstdint>

// ---------------- problem constants ----------------
#define NZ 9
#define ND 108          // depth cells (conv W dim)
#define NWC 124         // width cells (conv H dim)
#define NCELL 13392     // ND*NWC
#define NZN 120528      // NZ*NCELL
#define IMC_ 256
#define HC_ 2304        // 9*256
#define CATC 1280
#define OH1 62
#define OW1 54
#define OSP 3348        // 62*54

// level geometry
__device__ __constant__ int c_HH[5] = { 96, 48, 24, 12, 6 };
__device__ __constant__ int c_WW[5] = { 320, 160, 80, 40, 20 };
// float-offsets of per-level P buffers (HW*2304)
__device__ __constant__ int c_POFF[5]  = { 0, 70778880, 88473600, 92897280, 94003200 };
// cumulative M-tile (128) counts per level for the fused GEMM
__device__ __constant__ int c_MTCUM[6] = { 0, 240, 300, 315, 319, 320 };

// ---------------- scratch (device globals; no allocs allowed) ----------------
__device__ __align__(16) float g_P[94279680];       // all 5 levels, [z][hw][256] projected maps -> integral
__device__ __align__(16) float g_bbox[NZN * 4];
__device__ __align__(16) float g_wb[5 * 256 * HC_];   // [l][c][z*256+o] tf32-rounded weights
__device__ __align__(16) float g_xcat[CATC * NCELL];  // concat ortho [1280][124][108]
__device__ __align__(16) float g_w1s[CATC * 9 * IMC_];
__device__ __align__(16) float g_w2p[IMC_ * 9 * IMC_];
__device__ float g_colmean[CATC];
__device__ float g_sig[CATC];
__device__ __align__(16) float g_y1[IMC_ * OSP];
__device__ __align__(16) float g_c1part[4 * IMC_ * OSP];
__device__ __align__(16) float g_c2part[2 * IMC_ * OSP];

__device__ __forceinline__ float to_tf32(float x) {
    float r;
    asm("cvt.rna.tf32.f32 %0, %1;" : "=f"(r) : "f"(x));
    return r;
}

// ---------------- bbox projection ----------------
__device__ __forceinline__ float2 projnc(const float* __restrict__ P, int zi, int di, int wi) {
    float X = 0.64f * (float)di;
    float Y = 39.68f - 0.64f * (float)wi;
    float Z = 2.76f - 0.64f * (float)zi;
    float hx = P[0] * X + P[1] * Y + P[2]  * Z + P[3];
    float hy = P[4] * X + P[5] * Y + P[6]  * Z + P[7];
    float hz = P[8] * X + P[9] * Y + P[10] * Z + P[11];
    float ix = hx / hz, iy = hy / hz;
    float nx = fminf(fmaxf(2.0f * ix / 1280.0f - 1.0f, -1.0f), 1.0f);
    float ny = fminf(fmaxf(2.0f * iy / 384.0f  - 1.0f, -1.0f), 1.0f);
    return make_float2(nx, ny);
}

__global__ void k_bbox(const float* __restrict__ P) {
    int idx = blockIdx.x * 256 + threadIdx.x;
    if (idx >= NZN) return;
    int z = idx / NCELL;
    int r = idx - z * NCELL;
    int d = r / NWC;
    int w = r - d * NWC;
    float2 a = projnc(P, z,     d,     w);
    float2 b = projnc(P, z,     d + 1, w);
    float2 c = projnc(P, z + 1, d + 1, w + 1);
    float2 e = projnc(P, z + 1, d,     w + 1);
    g_bbox[idx * 4 + 0] = fminf(a.x, b.x);
    g_bbox[idx * 4 + 1] = fminf(a.y, b.y);
    g_bbox[idx * 4 + 2] = fmaxf(c.x, e.x);
    g_bbox[idx * 4 + 3] = fmaxf(c.y, e.y);
}

// ---------------- permute oft_w: g_wb[l][c][z*256+o] = tf32(w[l][o][c*9+z]) ----------------
__global__ void k_permwb(const float* __restrict__ w) {
    int idx = blockIdx.x * 256 + threadIdx.x;
    if (idx >= 5 * 256 * HC_) return;
    int zo = idx % HC_;
    int t = idx / HC_;
    int c = t & 255;
    int l = t >> 8;
    int z = zo >> 8, o = zo & 255;
    g_wb[idx] = to_tf32(w[((size_t)(l * IMC_ + o)) * HC_ + c * 9 + z]);
}

// ---------------- tf32 tensor-core GEMM: P[z][hw][o] = feats[c][hw]·W[c][zo] ----------------
#define SPAD 136
__global__ __launch_bounds__(256) void k_pgemm(
    const float* __restrict__ f0, const float* __restrict__ f1,
    const float* __restrict__ f2, const float* __restrict__ f3,
    const float* __restrict__ f4) {
    int bx = blockIdx.x;
    int l = 0;
    while (bx >= c_MTCUM[l + 1]) l++;
    int mtile = bx - c_MTCUM[l];
    int HW = c_HH[l] * c_WW[l];
    const float* __restrict__ Ag = (l == 0) ? f0 : (l == 1) ? f1 : (l == 2) ? f2 : (l == 3) ? f3 : f4;
    const float* __restrict__ Bg = g_wb + (size_t)l * 256 * HC_;
    float* __restrict__ P = g_P + c_POFF[l];

    __shared__ float As[2][16 * SPAD];
    __shared__ float Bs[2][16 * SPAD];

    int tid = threadIdx.x;
    int m0 = mtile * 128;
    int n0 = blockIdx.y * 128;

    int lane = tid & 31;
    int g = lane >> 2, t = lane & 3;
    int wid = tid >> 5;
    int wm = (wid & 1) * 64;
    int wn = (wid >> 1) * 32;

    float acc[4][4][4];
#pragma unroll
    for (int i = 0; i < 4; i++)
#pragma unroll
        for (int j = 0; j < 4; j++)
#pragma unroll
            for (int q = 0; q < 4; q++) acc[i][j][q] = 0.f;

    // per-thread load coords: two float4 each for A and B
    int ka0 = tid >> 5, ma0 = (tid & 31) * 4;            // idx = tid
    int ka1 = (tid + 256) >> 5, ma1 = ma0;               // idx = tid + 256

    // prologue: tile 0
    {
        float4 a0 = make_float4(0, 0, 0, 0), a1 = make_float4(0, 0, 0, 0);
        int gm0 = m0 + ma0, gm1 = m0 + ma1;
        if (gm0 < HW) a0 = *(const float4*)(Ag + (size_t)ka0 * HW + gm0);
        if (gm1 < HW) a1 = *(const float4*)(Ag + (size_t)ka1 * HW + gm1);
        float4 b0 = *(const float4*)(Bg + (size_t)ka0 * HC_ + n0 + ma0);
        float4 b1 = *(const float4*)(Bg + (size_t)ka1 * HC_ + n0 + ma1);
        As[0][ka0 * SPAD + ma0 + 0] = to_tf32(a0.x); As[0][ka0 * SPAD + ma0 + 1] = to_tf32(a0.y);
        As[0][ka0 * SPAD + ma0 + 2] = to_tf32(a0.z); As[0][ka0 * SPAD + ma0 + 3] = to_tf32(a0.w);
        As[0][ka1 * SPAD + ma1 + 0] = to_tf32(a1.x); As[0][ka1 * SPAD + ma1 + 1] = to_tf32(a1.y);
        As[0][ka1 * SPAD + ma1 + 2] = to_tf32(a1.z); As[0][ka1 * SPAD + ma1 + 3] = to_tf32(a1.w);
        *(float4*)&Bs[0][ka0 * SPAD + ma0] = b0;
        *(float4*)&Bs[0][ka1 * SPAD + ma1] = b1;
    }
    __syncthreads();

    const int NKT = 16;   // 256 / 16
    for (int kt = 0; kt < NKT; kt++) {
        int buf = kt & 1;
        float4 pa0 = make_float4(0, 0, 0, 0), pa1 = make_float4(0, 0, 0, 0);
        float4 pb0 = make_float4(0, 0, 0, 0), pb1 = make_float4(0, 0, 0, 0);
        if (kt + 1 < NKT) {
            int c0 = (kt + 1) * 16;
            int gm0 = m0 + ma0, gm1 = m0 + ma1;
            if (gm0 < HW) pa0 = *(const float4*)(Ag + (size_t)(c0 + ka0) * HW + gm0);
            if (gm1 < HW) pa1 = *(const float4*)(Ag + (size_t)(c0 + ka1) * HW + gm1);
            pb0 = *(const float4*)(Bg + (size_t)(c0 + ka0) * HC_ + n0 + ma0);
            pb1 = *(const float4*)(Bg + (size_t)(c0 + ka1) * HC_ + n0 + ma1);
        }
#pragma unroll
        for (int ks = 0; ks < 2; ks++) {
            int kk = ks * 8;
            uint32_t af[4][4], bf[4][2];
#pragma unroll
            for (int mf = 0; mf < 4; mf++) {
                int m = wm + mf * 16 + g;
                af[mf][0] = __float_as_uint(As[buf][(kk + t) * SPAD + m]);
                af[mf][1] = __float_as_uint(As[buf][(kk + t) * SPAD + m + 8]);
                af[mf][2] = __float_as_uint(As[buf][(kk + t + 4) * SPAD + m]);
                af[mf][3] = __float_as_uint(As[buf][(kk + t + 4) * SPAD + m + 8]);
            }
#pragma unroll
            for (int nf = 0; nf < 4; nf++) {
                int n = wn + nf * 8 + g;
                bf[nf][0] = __float_as_uint(Bs[buf][(kk + t) * SPAD + n]);
                bf[nf][1] = __float_as_uint(Bs[buf][(kk + t + 4) * SPAD + n]);
            }
#pragma unroll
            for (int mf = 0; mf < 4; mf++)
#pragma unroll
                for (int nf = 0; nf < 4; nf++) {
                    asm volatile(
                        "mma.sync.aligned.m16n8k8.row.col.f32.tf32.tf32.f32 "
                        "{%0,%1,%2,%3}, {%4,%5,%6,%7}, {%8,%9}, {%0,%1,%2,%3};"
                        : "+f"(acc[mf][nf][0]), "+f"(acc[mf][nf][1]),
                          "+f"(acc[mf][nf][2]), "+f"(acc[mf][nf][3])
                        : "r"(af[mf][0]), "r"(af[mf][1]), "r"(af[mf][2]), "r"(af[mf][3]),
                          "r"(bf[nf][0]), "r"(bf[nf][1]));
                }
        }
        if (kt + 1 < NKT) {
            int nb = buf ^ 1;
            As[nb][ka0 * SPAD + ma0 + 0] = to_tf32(pa0.x); As[nb][ka0 * SPAD + ma0 + 1] = to_tf32(pa0.y);
            As[nb][ka0 * SPAD + ma0 + 2] = to_tf32(pa0.z); As[nb][ka0 * SPAD + ma0 + 3] = to_tf32(pa0.w);
            As[nb][ka1 * SPAD + ma1 + 0] = to_tf32(pa1.x); As[nb][ka1 * SPAD + ma1 + 1] = to_tf32(pa1.y);
            As[nb][ka1 * SPAD + ma1 + 2] = to_tf32(pa1.z); As[nb][ka1 * SPAD + ma1 + 3] = to_tf32(pa1.w);
            *(float4*)&Bs[nb][ka0 * SPAD + ma0] = pb0;
            *(float4*)&Bs[nb][ka1 * SPAD + ma1] = pb1;
        }
        __syncthreads();
    }

    // epilogue: store to P[z][hw][o]; n-tile (128) lies within one z
    int z = n0 >> 8;
    int ob0 = n0 & 255;
#pragma unroll
    for (int mf = 0; mf < 4; mf++) {
        int m = m0 + wm + mf * 16 + g;
#pragma unroll
        for (int nf = 0; nf < 4; nf++) {
            int o = ob0 + wn + nf * 8 + 2 * t;
            if (m < HW) {
                float* dst = P + ((size_t)z * HW + m) * 256 + o;
                *(float2*)dst = make_float2(acc[mf][nf][0], acc[mf][nf][1]);
            }
            if (m + 8 < HW) {
                float* dst = P + ((size_t)z * HW + m + 8) * 256 + o;
                *(float2*)dst = make_float2(acc[mf][nf][2], acc[mf][nf][3]);
            }
        }
    }
}

// ---------------- cumsum of P along w then h (per level) ----------------
__global__ void k_prow(int l, int H, int W) {
    int t = blockIdx.x * 256 + threadIdx.x;
    if (t >= NZ * H * 256) return;
    int o = t & 255;
    int r = t >> 8;
    int h = r % H, z = r / H;
    float* p = g_P + c_POFF[l] + ((size_t)(z * H + h) * W) * 256 + o;
    float a = 0.f;
    for (int w = 0; w < W; w++) { int off = w * 256; a += p[off]; p[off] = a; }
}

__global__ void k_pcol(int l, int H, int W) {
    int t = blockIdx.x * 256 + threadIdx.x;
    if (t >= NZ * W * 256) return;
    int o = t & 255;
    int r = t >> 8;
    int w = r % W, z = r / W;
    float* p = g_P + c_POFF[l] + ((size_t)z * H * W + w) * 256 + o;
    float a = 0.f;
    int stride = W * 256;
    for (int h = 0; h < H; h++) { int off = h * stride; a += p[off]; p[off] = a; }
}

// ---------------- fused gather: ortho[n][o] = relu(b + sum_z sum_taps w*P) ----------------
__global__ __launch_bounds__(256) void k_gather(const float* __restrict__ bias) {
    int n = blockIdx.x;
    int l = blockIdx.y;
    int o = threadIdx.x;
    int Hf = c_HH[l], Wf = c_WW[l];
    int HW = Hf * Wf;
    float areaF = (float)(Hf * Wf) * 0.25f;
    const float* __restrict__ P = g_P + c_POFF[l];

    float acc = bias[l * 256 + o];

    for (int z = 0; z < NZ; z++) {
        float4 bb = *(const float4*)&g_bbox[(z * NCELL + n) * 4];
        float area = (bb.z - bb.x) * (bb.w - bb.y) * areaF + 1e-6f;
        if (!(area > 1e-6f)) continue;
        float inv = 1.0f / area;

        float cwv[4]; int coff[4];
        {
            float xs[2] = { bb.x, bb.z };
#pragma unroll
            for (int s = 0; s < 2; s++) {
                float x = (xs[s] + 1.f) * (Wf * 0.5f) - 0.5f;
                float xf = floorf(x);
                float wx = x - xf;
                int xi = (int)xf;
                float sg = s ? -1.f : 1.f;
                bool ok0 = (xi >= 0) && (xi < Wf);
                bool ok1 = (xi + 1 >= 0) && (xi + 1 < Wf);
                cwv[s * 2 + 0] = ok0 ? sg * (1.f - wx) : 0.f;
                cwv[s * 2 + 1] = ok1 ? sg * wx : 0.f;
                coff[s * 2 + 0] = ok0 ? xi * 256 : 0;
                coff[s * 2 + 1] = ok1 ? (xi + 1) * 256 : 0;
            }
        }
        float rwv[4]; int roff[4];
        {
            float ys[2] = { bb.y, bb.w };
#pragma unroll
            for (int s = 0; s < 2; s++) {
                float y = (ys[s] + 1.f) * (Hf * 0.5f) - 0.5f;
                float yf = floorf(y);
                float wy = y - yf;
                int yi = (int)yf;
                float sg = s ? -1.f : 1.f;
                bool ok0 = (yi >= 0) && (yi < Hf);
                bool ok1 = (yi + 1 >= 0) && (yi + 1 < Hf);
                rwv[s * 2 + 0] = ok0 ? sg * (1.f - wy) * inv : 0.f;
                rwv[s * 2 + 1] = ok1 ? sg * wy * inv : 0.f;
                roff[s * 2 + 0] = ok0 ? yi * Wf * 256 : 0;
                roff[s * 2 + 1] = ok1 ? (yi + 1) * Wf * 256 : 0;
            }
        }
        const float* Pz = P + (size_t)z * HW * 256 + o;
#pragma unroll
        for (int j = 0; j < 4; j++) {
            const float* Pr = Pz + roff[j];
            float rs = cwv[0] * Pr[coff[0]] + cwv[1] * Pr[coff[1]]
                     + cwv[2] * Pr[coff[2]] + cwv[3] * Pr[coff[3]];
            acc += rwv[j] * rs;
        }
    }
    int d = n / NWC, w = n - d * NWC;
    int sp = w * ND + d;
    g_xcat[(l * 256 + o) * NCELL + sp] = fmaxf(acc, 0.0f);
}

// ---------------- channel means ----------------
__global__ void k_colmean() {
    int g = blockIdx.x;
    const float* p = g_xcat + g * NCELL;
    float s = 0.f;
    for (int i = threadIdx.x; i < NCELL; i += 256) s += p[i];
    __shared__ float sm[256];
    sm[threadIdx.x] = s;
    __syncthreads();
    for (int st = 128; st > 0; st >>= 1) {
        if (threadIdx.x < st) sm[threadIdx.x] += sm[threadIdx.x + st];
        __syncthreads();
    }
    if (threadIdx.x == 0) g_colmean[g] = sm[0] * (1.0f / (float)NCELL);
}

__global__ void k_att(const float* __restrict__ aw, const float* __restrict__ ab) {
    __shared__ float cm[IMC_];
    int l = blockIdx.x, o = threadIdx.x;
    cm[o] = g_colmean[l * IMC_ + o];
    __syncthreads();
    float acc = ab[o];
    for (int c = 0; c < IMC_; c++) acc += cm[c] * aw[o * IMC_ + c];
    g_sig[l * IMC_ + o] = 1.0f / (1.0f + expf(-acc));
}

// ---------------- fold attention + transpose conv1 weights: [cin][kk][o] ----------------
__global__ void k_wscale(const float* __restrict__ w) {
    int idx = blockIdx.x * 256 + threadIdx.x;
    if (idx >= CATC * 9 * IMC_) return;
    int o = idx & 255;
    int t = idx >> 8;
    int kk = t % 9;
    int cin = t / 9;
    g_w1s[idx] = w[(o * CATC + cin) * 9 + kk] * g_sig[cin];
}

__global__ void k_permw2(const float* __restrict__ w) {
    int idx = blockIdx.x * 256 + threadIdx.x;
    if (idx >= IMC_ * 9 * IMC_) return;
    int o = idx & 255;
    int t = idx >> 8;
    int kk = t % 9;
    int cin = t / 9;
    g_w2p[idx] = w[(o * IMC_ + cin) * 9 + kk];
}

// ---------------- conv1: 3x3 s2 p1, 1280->256, cin-split x4 partials ----------------
__global__ __launch_bounds__(256) void k_conv1() {
    int tid = threadIdx.x;
    int ob = blockIdx.y * 16;
    int c0 = blockIdx.z * 320;
    int p0 = blockIdx.x * 512 + tid;
    int p1 = p0 + 256;
    bool v0 = p0 < OSP, v1 = p1 < OSP;
    int q0 = v0 ? p0 : 0, q1 = v1 ? p1 : 0;
    int oh0 = q0 / OW1, ow0 = q0 - oh0 * OW1;
    int oh1 = q1 / OW1, ow1 = q1 - oh1 * OW1;

    float acc0[16], acc1[16];
#pragma unroll
    for (int t = 0; t < 16; t++) { acc0[t] = 0.f; acc1[t] = 0.f; }

    for (int cin = c0; cin < c0 + 320; cin++) {
        const float* xc = g_xcat + cin * NCELL;
        const float* wrow = g_w1s + cin * 9 * 256 + ob;
#pragma unroll
        for (int ky = 0; ky < 3; ky++) {
            int ih0 = 2 * oh0 + ky - 1;
            int ih1 = 2 * oh1 + ky - 1;
#pragma unroll
            for (int kx = 0; kx < 3; kx++) {
                int iw0 = 2 * ow0 + kx - 1;
                int iw1 = 2 * ow1 + kx - 1;
                float x0 = (ih0 >= 0 && ih0 < NWC && iw0 >= 0 && iw0 < ND) ? xc[ih0 * ND + iw0] : 0.f;
                float x1 = (ih1 >= 0 && ih1 < NWC && iw1 >= 0 && iw1 < ND) ? xc[ih1 * ND + iw1] : 0.f;
                const float4* wv = (const float4*)(wrow + (ky * 3 + kx) * 256);
#pragma unroll
                for (int q = 0; q < 4; q++) {
                    float4 w4 = wv[q];
                    acc0[q * 4 + 0] += x0 * w4.x; acc1[q * 4 + 0] += x1 * w4.x;
                    acc0[q * 4 + 1] += x0 * w4.y; acc1[q * 4 + 1] += x1 * w4.y;
                    acc0[q * 4 + 2] += x0 * w4.z; acc1[q * 4 + 2] += x1 * w4.z;
                    acc0[q * 4 + 3] += x0 * w4.w; acc1[q * 4 + 3] += x1 * w4.w;
                }
            }
        }
    }
    float* part = g_c1part + blockIdx.z * IMC_ * OSP;
#pragma unroll
    for (int t = 0; t < 16; t++) {
        int o = ob + t;
        if (v0) part[o * OSP + p0] = acc0[t];
        if (v1) part[o * OSP + p1] = acc1[t];
    }
}

__global__ void k_c1red(const float* __restrict__ bg, const float* __restrict__ bb,
                        const float* __restrict__ bm, const float* __restrict__ bv) {
    int idx = blockIdx.x * 256 + threadIdx.x;
    if (idx >= IMC_ * OSP) return;
    int o = idx / OSP;
    float s = g_c1part[idx] + g_c1part[IMC_ * OSP + idx]
            + g_c1part[2 * IMC_ * OSP + idx] + g_c1part[3 * IMC_ * OSP + idx];
    float sc = bg[o] / sqrtf(bv[o] + 1e-5f);
    g_y1[idx] = fmaxf((s - bm[o]) * sc + bb[o], 0.f);
}

// ---------------- conv2: 3x3 s1 p1, 256->256, cin-split x2 partials ----------------
__global__ __launch_bounds__(256) void k_conv2() {
    int tid = threadIdx.x;
    int ob = blockIdx.y * 16;
    int c0 = blockIdx.z * 128;
    int p0 = blockIdx.x * 512 + tid;
    int p1 = p0 + 256;
    bool v0 = p0 < OSP, v1 = p1 < OSP;
    int q0 = v0 ? p0 : 0, q1 = v1 ? p1 : 0;
    int oh0 = q0 / OW1, ow0 = q0 - oh0 * OW1;
    int oh1 = q1 / OW1, ow1 = q1 - oh1 * OW1;

    float acc0[16], acc1[16];
#pragma unroll
    for (int t = 0; t < 16; t++) { acc0[t] = 0.f; acc1[t] = 0.f; }

    for (int cin = c0; cin < c0 + 128; cin++) {
        const float* xc = g_y1 + cin * OSP;
        const float* wrow = g_w2p + cin * 9 * 256 + ob;
#pragma unroll
        for (int ky = 0; ky < 3; ky++) {
            int ih0 = oh0 + ky - 1;
            int ih1 = oh1 + ky - 1;
#pragma unroll
            for (int kx = 0; kx < 3; kx++) {
                int iw0 = ow0 + kx - 1;
                int iw1 = ow1 + kx - 1;
                float x0 = (ih0 >= 0 && ih0 < OH1 && iw0 >= 0 && iw0 < OW1) ? xc[ih0 * OW1 + iw0] : 0.f;
                float x1 = (ih1 >= 0 && ih1 < OH1 && iw1 >= 0 && iw1 < OW1) ? xc[ih1 * OW1 + iw1] : 0.f;
                const float4* wv = (const float4*)(wrow + (ky * 3 + kx) * 256);
#pragma unroll
                for (int q = 0; q < 4; q++) {
                    float4 w4 = wv[q];
                    acc0[q * 4 + 0] += x0 * w4.x; acc1[q * 4 + 0] += x1 * w4.x;
                    acc0[q * 4 + 1] += x0 * w4.y; acc1[q * 4 + 1] += x1 * w4.y;
                    acc0[q * 4 + 2] += x0 * w4.z; acc1[q * 4 + 2] += x1 * w4.z;
                    acc0[q * 4 + 3] += x0 * w4.w; acc1[q * 4 + 3] += x1 * w4.w;
                }
            }
        }
    }
    float* part = g_c2part + blockIdx.z * IMC_ * OSP;
#pragma unroll
    for (int t = 0; t < 16; t++) {
        int o = ob + t;
        if (v0) part[o * OSP + p0] = acc0[t];
        if (v1) part[o * OSP + p1] = acc1[t];
    }
}

__global__ void k_c2red(const float* __restrict__ bg, const float* __restrict__ bb,
                        const float* __restrict__ bm, const float* __restrict__ bv,
                        float* __restrict__ out) {
    int idx = blockIdx.x * 256 + threadIdx.x;
    if (idx >= IMC_ * OSP) return;
    int o = idx / OSP;
    float s = g_c2part[idx] + g_c2part[IMC_ * OSP + idx];
    float sc = bg[o] / sqrtf(bv[o] + 1e-5f);
    out[idx] = fmaxf((s - bm[o]) * sc + bb[o], 0.f);
}

// ---------------- launch ----------------
extern "C" void kernel_launch(void* const* d_in, const int* in_sizes, int n_in,
                              void* d_out, int out_size) {
    (void)in_sizes; (void)n_in; (void)out_size;
    const float* f0 = (const float*)d_in[0];
    const float* f1 = (const float*)d_in[1];
    const float* f2 = (const float*)d_in[2];
    const float* f3 = (const float*)d_in[3];
    const float* f4 = (const float*)d_in[4];
    const float* calib = (const float*)d_in[5];
    const float* oftw  = (const float*)d_in[6];
    const float* oftb  = (const float*)d_in[7];
    const float* attw  = (const float*)d_in[8];
    const float* attb  = (const float*)d_in[9];
    const float* c1w   = (const float*)d_in[10];
    const float* b1g   = (const float*)d_in[11];
    const float* b1b   = (const float*)d_in[12];
    const float* b1m   = (const float*)d_in[13];
    const float* b1v   = (const float*)d_in[14];
    const float* c2w   = (const float*)d_in[15];
    const float* b2g   = (const float*)d_in[16];
    const float* b2b   = (const float*)d_in[17];
    const float* b2m   = (const float*)d_in[18];
    const float* b2v   = (const float*)d_in[19];
    float* out = (float*)d_out;

    k_bbox<<<(NZN + 255) / 256, 256>>>(calib);
    k_permwb<<<(5 * 256 * HC_ + 255) / 256, 256>>>(oftw);
    k_permw2<<<(IMC_ * 9 * IMC_ + 255) / 256, 256>>>(c2w);

    k_pgemm<<<dim3(320, 18), 256>>>(f0, f1, f2, f3, f4);

    static const int HH[5] = { 96, 48, 24, 12, 6 };
    static const int WW[5] = { 320, 160, 80, 40, 20 };
    for (int l = 0; l < 5; l++) {
        int H = HH[l], W = WW[l];
        k_prow<<<(NZ * H * 256 + 255) / 256, 256>>>(l, H, W);
        k_pcol<<<(NZ * W * 256 + 255) / 256, 256>>>(l, H, W);
    }
    k_gather<<<dim3(NCELL, 5), 256>>>(oftb);

    k_colmean<<<CATC, 256>>>();
    k_att<<<5, 256>>>(attw, attb);
    k_wscale<<<(CATC * 9 * IMC_ + 255) / 256, 256>>>(c1w);
    k_conv1<<<dim3(7, 16, 4), 256>>>();
    k_c1red<<<(IMC_ * OSP + 255) / 256, 256>>>(b1g, b1b, b1m, b1v);
    k_conv2<<<dim3(7, 16, 2), 256>>>();
    k_c2red<<<(IMC_ * OSP + 255) / 256, 256>>>(b2g, b2b, b2m, b2v, out);
}

// round 5
// speedup vs baseline: 6.2290x; 1.8866x over previous
#include <cuda_runtime.h>
#include <cstdint>

// ---------------- problem constants ----------------
#define NZ 9
#define ND 108          // depth cells (conv W dim)
#define NWC 124         // width cells (conv H dim)
#define NCELL 13392     // ND*NWC
#define NZN 120528      // NZ*NCELL
#define IMC_ 256
#define HC_ 2304        // 9*256
#define CATC 1280
#define OH1 62
#define OW1 54
#define OSP 3348        // 62*54

// level geometry
__device__ __constant__ int c_HH[5] = { 96, 48, 24, 12, 6 };
__device__ __constant__ int c_WW[5] = { 320, 160, 80, 40, 20 };
// float-offsets of per-level P buffers (HW*2304)
__device__ __constant__ int c_POFF[5]  = { 0, 70778880, 88473600, 92897280, 94003200 };
// cumulative M-tile (128) counts per level for the fused GEMM
__device__ __constant__ int c_MTCUM[6] = { 0, 240, 300, 315, 319, 320 };
// cumulative thread counts for merged cumsum kernels
__device__ __constant__ int c_RCUM[6] = { 0, 221184, 331776, 387072, 414720, 428544 };
__device__ __constant__ int c_CCUM[6] = { 0, 737280, 1105920, 1290240, 1382400, 1428480 };

// ---------------- scratch (device globals; no allocs allowed) ----------------
__device__ __align__(16) float g_P[94279680];       // all 5 levels, [z][hw][256] projected maps -> integral
__device__ __align__(16) float g_bbox[NZN * 4];
__device__ __align__(16) float g_wb[5 * 256 * HC_];   // [l][c][z*256+o] tf32-rounded weights
__device__ __align__(16) float g_xcat[CATC * NCELL];  // concat ortho [1280][124][108]
__device__ __align__(16) float g_w1s[CATC * 9 * IMC_]; // [k=cin*9+kk][o], tf32, attention-folded
__device__ __align__(16) float g_w2p[IMC_ * 9 * IMC_]; // [k][o], tf32
__device__ float g_colmean[CATC];
__device__ float g_sig[CATC];
__device__ __align__(16) float g_y1[IMC_ * OSP];
__device__ __align__(16) float g_c1part[4 * IMC_ * OSP];
__device__ __align__(16) float g_c2part[2 * IMC_ * OSP];

__device__ __forceinline__ float to_tf32(float x) {
    float r;
    asm("cvt.rna.tf32.f32 %0, %1;" : "=f"(r) : "f"(x));
    return r;
}

// ---------------- bbox projection ----------------
__device__ __forceinline__ float2 projnc(const float* __restrict__ P, int zi, int di, int wi) {
    float X = 0.64f * (float)di;
    float Y = 39.68f - 0.64f * (float)wi;
    float Z = 2.76f - 0.64f * (float)zi;
    float hx = P[0] * X + P[1] * Y + P[2]  * Z + P[3];
    float hy = P[4] * X + P[5] * Y + P[6]  * Z + P[7];
    float hz = P[8] * X + P[9] * Y + P[10] * Z + P[11];
    float ix = hx / hz, iy = hy / hz;
    float nx = fminf(fmaxf(2.0f * ix / 1280.0f - 1.0f, -1.0f), 1.0f);
    float ny = fminf(fmaxf(2.0f * iy / 384.0f  - 1.0f, -1.0f), 1.0f);
    return make_float2(nx, ny);
}

__global__ void k_bbox(const float* __restrict__ P) {
    int idx = blockIdx.x * 256 + threadIdx.x;
    if (idx >= NZN) return;
    int z = idx / NCELL;
    int r = idx - z * NCELL;
    int d = r / NWC;
    int w = r - d * NWC;
    float2 a = projnc(P, z,     d,     w);
    float2 b = projnc(P, z,     d + 1, w);
    float2 c = projnc(P, z + 1, d + 1, w + 1);
    float2 e = projnc(P, z + 1, d,     w + 1);
    g_bbox[idx * 4 + 0] = fminf(a.x, b.x);
    g_bbox[idx * 4 + 1] = fminf(a.y, b.y);
    g_bbox[idx * 4 + 2] = fmaxf(c.x, e.x);
    g_bbox[idx * 4 + 3] = fmaxf(c.y, e.y);
}

// ---------------- permute oft_w: g_wb[l][c][z*256+o] = tf32(w[l][o][c*9+z]) ----------------
__global__ void k_permwb(const float* __restrict__ w) {
    int idx = blockIdx.x * 256 + threadIdx.x;
    if (idx >= 5 * 256 * HC_) return;
    int zo = idx % HC_;
    int t = idx / HC_;
    int c = t & 255;
    int l = t >> 8;
    int z = zo >> 8, o = zo & 255;
    g_wb[idx] = to_tf32(w[((size_t)(l * IMC_ + o)) * HC_ + c * 9 + z]);
}

// ---------------- tf32 tensor-core GEMM: P[z][hw][o] = feats[c][hw]·W[c][zo] ----------------
#define SPAD 136
__global__ __launch_bounds__(256) void k_pgemm(
    const float* __restrict__ f0, const float* __restrict__ f1,
    const float* __restrict__ f2, const float* __restrict__ f3,
    const float* __restrict__ f4) {
    int bx = blockIdx.x;
    int l = 0;
    while (bx >= c_MTCUM[l + 1]) l++;
    int mtile = bx - c_MTCUM[l];
    int HW = c_HH[l] * c_WW[l];
    const float* __restrict__ Ag = (l == 0) ? f0 : (l == 1) ? f1 : (l == 2) ? f2 : (l == 3) ? f3 : f4;
    const float* __restrict__ Bg = g_wb + (size_t)l * 256 * HC_;
    float* __restrict__ P = g_P + c_POFF[l];

    __shared__ float As[2][16 * SPAD];
    __shared__ float Bs[2][16 * SPAD];

    int tid = threadIdx.x;
    int m0 = mtile * 128;
    int n0 = blockIdx.y * 128;

    int lane = tid & 31;
    int g = lane >> 2, t = lane & 3;
    int wid = tid >> 5;
    int wm = (wid & 1) * 64;
    int wn = (wid >> 1) * 32;

    float acc[4][4][4];
#pragma unroll
    for (int i = 0; i < 4; i++)
#pragma unroll
        for (int j = 0; j < 4; j++)
#pragma unroll
            for (int q = 0; q < 4; q++) acc[i][j][q] = 0.f;

    int ka0 = tid >> 5, ma0 = (tid & 31) * 4;
    int ka1 = (tid + 256) >> 5, ma1 = ma0;

    {
        float4 a0 = make_float4(0, 0, 0, 0), a1 = make_float4(0, 0, 0, 0);
        int gm0 = m0 + ma0, gm1 = m0 + ma1;
        if (gm0 < HW) a0 = *(const float4*)(Ag + (size_t)ka0 * HW + gm0);
        if (gm1 < HW) a1 = *(const float4*)(Ag + (size_t)ka1 * HW + gm1);
        float4 b0 = *(const float4*)(Bg + (size_t)ka0 * HC_ + n0 + ma0);
        float4 b1 = *(const float4*)(Bg + (size_t)ka1 * HC_ + n0 + ma1);
        As[0][ka0 * SPAD + ma0 + 0] = to_tf32(a0.x); As[0][ka0 * SPAD + ma0 + 1] = to_tf32(a0.y);
        As[0][ka0 * SPAD + ma0 + 2] = to_tf32(a0.z); As[0][ka0 * SPAD + ma0 + 3] = to_tf32(a0.w);
        As[0][ka1 * SPAD + ma1 + 0] = to_tf32(a1.x); As[0][ka1 * SPAD + ma1 + 1] = to_tf32(a1.y);
        As[0][ka1 * SPAD + ma1 + 2] = to_tf32(a1.z); As[0][ka1 * SPAD + ma1 + 3] = to_tf32(a1.w);
        *(float4*)&Bs[0][ka0 * SPAD + ma0] = b0;
        *(float4*)&Bs[0][ka1 * SPAD + ma1] = b1;
    }
    __syncthreads();

    const int NKT = 16;
    for (int kt = 0; kt < NKT; kt++) {
        int buf = kt & 1;
        float4 pa0 = make_float4(0, 0, 0, 0), pa1 = make_float4(0, 0, 0, 0);
        float4 pb0 = make_float4(0, 0, 0, 0), pb1 = make_float4(0, 0, 0, 0);
        if (kt + 1 < NKT) {
            int c0 = (kt + 1) * 16;
            int gm0 = m0 + ma0, gm1 = m0 + ma1;
            if (gm0 < HW) pa0 = *(const float4*)(Ag + (size_t)(c0 + ka0) * HW + gm0);
            if (gm1 < HW) pa1 = *(const float4*)(Ag + (size_t)(c0 + ka1) * HW + gm1);
            pb0 = *(const float4*)(Bg + (size_t)(c0 + ka0) * HC_ + n0 + ma0);
            pb1 = *(const float4*)(Bg + (size_t)(c0 + ka1) * HC_ + n0 + ma1);
        }
#pragma unroll
        for (int ks = 0; ks < 2; ks++) {
            int kk = ks * 8;
            uint32_t af[4][4], bf[4][2];
#pragma unroll
            for (int mf = 0; mf < 4; mf++) {
                int m = wm + mf * 16 + g;
                af[mf][0] = __float_as_uint(As[buf][(kk + t) * SPAD + m]);
                af[mf][1] = __float_as_uint(As[buf][(kk + t) * SPAD + m + 8]);
                af[mf][2] = __float_as_uint(As[buf][(kk + t + 4) * SPAD + m]);
                af[mf][3] = __float_as_uint(As[buf][(kk + t + 4) * SPAD + m + 8]);
            }
#pragma unroll
            for (int nf = 0; nf < 4; nf++) {
                int n = wn + nf * 8 + g;
                bf[nf][0] = __float_as_uint(Bs[buf][(kk + t) * SPAD + n]);
                bf[nf][1] = __float_as_uint(Bs[buf][(kk + t + 4) * SPAD + n]);
            }
#pragma unroll
            for (int mf = 0; mf < 4; mf++)
#pragma unroll
                for (int nf = 0; nf < 4; nf++) {
                    asm volatile(
                        "mma.sync.aligned.m16n8k8.row.col.f32.tf32.tf32.f32 "
                        "{%0,%1,%2,%3}, {%4,%5,%6,%7}, {%8,%9}, {%0,%1,%2,%3};"
                        : "+f"(acc[mf][nf][0]), "+f"(acc[mf][nf][1]),
                          "+f"(acc[mf][nf][2]), "+f"(acc[mf][nf][3])
                        : "r"(af[mf][0]), "r"(af[mf][1]), "r"(af[mf][2]), "r"(af[mf][3]),
                          "r"(bf[nf][0]), "r"(bf[nf][1]));
                }
        }
        if (kt + 1 < NKT) {
            int nb = buf ^ 1;
            As[nb][ka0 * SPAD + ma0 + 0] = to_tf32(pa0.x); As[nb][ka0 * SPAD + ma0 + 1] = to_tf32(pa0.y);
            As[nb][ka0 * SPAD + ma0 + 2] = to_tf32(pa0.z); As[nb][ka0 * SPAD + ma0 + 3] = to_tf32(pa0.w);
            As[nb][ka1 * SPAD + ma1 + 0] = to_tf32(pa1.x); As[nb][ka1 * SPAD + ma1 + 1] = to_tf32(pa1.y);
            As[nb][ka1 * SPAD + ma1 + 2] = to_tf32(pa1.z); As[nb][ka1 * SPAD + ma1 + 3] = to_tf32(pa1.w);
            *(float4*)&Bs[nb][ka0 * SPAD + ma0] = pb0;
            *(float4*)&Bs[nb][ka1 * SPAD + ma1] = pb1;
        }
        __syncthreads();
    }

    int z = n0 >> 8;
    int ob0 = n0 & 255;
#pragma unroll
    for (int mf = 0; mf < 4; mf++) {
        int m = m0 + wm + mf * 16 + g;
#pragma unroll
        for (int nf = 0; nf < 4; nf++) {
            int o = ob0 + wn + nf * 8 + 2 * t;
            if (m < HW) {
                float* dst = P + ((size_t)z * HW + m) * 256 + o;
                *(float2*)dst = make_float2(acc[mf][nf][0], acc[mf][nf][1]);
            }
            if (m + 8 < HW) {
                float* dst = P + ((size_t)z * HW + m + 8) * 256 + o;
                *(float2*)dst = make_float2(acc[mf][nf][2], acc[mf][nf][3]);
            }
        }
    }
}

// ---------------- merged cumsum of P along w (all levels) ----------------
__global__ void k_prow(void) {
    int t = blockIdx.x * 256 + threadIdx.x;
    if (t >= 428544) return;
    int l = 0;
    while (t >= c_RCUM[l + 1]) l++;
    int tt = t - c_RCUM[l];
    int H = c_HH[l], W = c_WW[l];
    int o = tt & 255;
    int r = tt >> 8;
    int h = r % H, z = r / H;
    float* p = g_P + c_POFF[l] + ((size_t)(z * H + h) * W) * 256 + o;
    float a = 0.f;
    for (int w = 0; w < W; w++) { int off = w * 256; a += p[off]; p[off] = a; }
}

// ---------------- merged cumsum of P along h (all levels) ----------------
__global__ void k_pcol(void) {
    int t = blockIdx.x * 256 + threadIdx.x;
    if (t >= 1428480) return;
    int l = 0;
    while (t >= c_CCUM[l + 1]) l++;
    int tt = t - c_CCUM[l];
    int H = c_HH[l], W = c_WW[l];
    int o = tt & 255;
    int r = tt >> 8;
    int w = r % W, z = r / W;
    float* p = g_P + c_POFF[l] + ((size_t)z * H * W + w) * 256 + o;
    float a = 0.f;
    int stride = W * 256;
    for (int h = 0; h < H; h++) { int off = h * stride; a += p[off]; p[off] = a; }
}

// ---------------- fused gather: ortho[n][o] = relu(b + sum_z sum_taps w*P) ----------------
__global__ __launch_bounds__(256) void k_gather(const float* __restrict__ bias) {
    int n = blockIdx.x;
    int l = blockIdx.y;
    int o = threadIdx.x;
    int Hf = c_HH[l], Wf = c_WW[l];
    int HW = Hf * Wf;
    float areaF = (float)(Hf * Wf) * 0.25f;
    const float* __restrict__ P = g_P + c_POFF[l];

    float acc = bias[l * 256 + o];

    for (int z = 0; z < NZ; z++) {
        float4 bb = *(const float4*)&g_bbox[(z * NCELL + n) * 4];
        float area = (bb.z - bb.x) * (bb.w - bb.y) * areaF + 1e-6f;
        if (!(area > 1e-6f)) continue;
        float inv = 1.0f / area;

        float cwv[4]; int coff[4];
        {
            float xs[2] = { bb.x, bb.z };
#pragma unroll
            for (int s = 0; s < 2; s++) {
                float x = (xs[s] + 1.f) * (Wf * 0.5f) - 0.5f;
                float xf = floorf(x);
                float wx = x - xf;
                int xi = (int)xf;
                float sg = s ? -1.f : 1.f;
                bool ok0 = (xi >= 0) && (xi < Wf);
                bool ok1 = (xi + 1 >= 0) && (xi + 1 < Wf);
                cwv[s * 2 + 0] = ok0 ? sg * (1.f - wx) : 0.f;
                cwv[s * 2 + 1] = ok1 ? sg * wx : 0.f;
                coff[s * 2 + 0] = ok0 ? xi * 256 : 0;
                coff[s * 2 + 1] = ok1 ? (xi + 1) * 256 : 0;
            }
        }
        float rwv[4]; int roff[4];
        {
            float ys[2] = { bb.y, bb.w };
#pragma unroll
            for (int s = 0; s < 2; s++) {
                float y = (ys[s] + 1.f) * (Hf * 0.5f) - 0.5f;
                float yf = floorf(y);
                float wy = y - yf;
                int yi = (int)yf;
                float sg = s ? -1.f : 1.f;
                bool ok0 = (yi >= 0) && (yi < Hf);
                bool ok1 = (yi + 1 >= 0) && (yi + 1 < Hf);
                rwv[s * 2 + 0] = ok0 ? sg * (1.f - wy) * inv : 0.f;
                rwv[s * 2 + 1] = ok1 ? sg * wy * inv : 0.f;
                roff[s * 2 + 0] = ok0 ? yi * Wf * 256 : 0;
                roff[s * 2 + 1] = ok1 ? (yi + 1) * Wf * 256 : 0;
            }
        }
        const float* Pz = P + (size_t)z * HW * 256 + o;
#pragma unroll
        for (int j = 0; j < 4; j++) {
            const float* Pr = Pz + roff[j];
            float rs = cwv[0] * Pr[coff[0]] + cwv[1] * Pr[coff[1]]
                     + cwv[2] * Pr[coff[2]] + cwv[3] * Pr[coff[3]];
            acc += rwv[j] * rs;
        }
    }
    int d = n / NWC, w = n - d * NWC;
    int sp = w * ND + d;
    g_xcat[(l * 256 + o) * NCELL + sp] = fmaxf(acc, 0.0f);
}

// ---------------- channel means ----------------
__global__ void k_colmean() {
    int g = blockIdx.x;
    const float* p = g_xcat + g * NCELL;
    float s = 0.f;
    for (int i = threadIdx.x; i < NCELL; i += 256) s += p[i];
    __shared__ float sm[256];
    sm[threadIdx.x] = s;
    __syncthreads();
    for (int st = 128; st > 0; st >>= 1) {
        if (threadIdx.x < st) sm[threadIdx.x] += sm[threadIdx.x + st];
        __syncthreads();
    }
    if (threadIdx.x == 0) g_colmean[g] = sm[0] * (1.0f / (float)NCELL);
}

__global__ void k_att(const float* __restrict__ aw, const float* __restrict__ ab) {
    __shared__ float cm[IMC_];
    int l = blockIdx.x, o = threadIdx.x;
    cm[o] = g_colmean[l * IMC_ + o];
    __syncthreads();
    float acc = ab[o];
    for (int c = 0; c < IMC_; c++) acc += cm[c] * aw[o * IMC_ + c];
    g_sig[l * IMC_ + o] = 1.0f / (1.0f + expf(-acc));
}

// ---------------- fold attention + transpose conv1 weights -> tf32 [k][o] ----------------
__global__ void k_wscale(const float* __restrict__ w) {
    int idx = blockIdx.x * 256 + threadIdx.x;
    if (idx >= CATC * 9 * IMC_) return;
    int o = idx & 255;
    int t = idx >> 8;
    int kk = t % 9;
    int cin = t / 9;
    g_w1s[idx] = to_tf32(w[(o * CATC + cin) * 9 + kk] * g_sig[cin]);
}

__global__ void k_permw2(const float* __restrict__ w) {
    int idx = blockIdx.x * 256 + threadIdx.x;
    if (idx >= IMC_ * 9 * IMC_) return;
    int o = idx & 255;
    int t = idx >> 8;
    int kk = t % 9;
    int cin = t / 9;
    g_w2p[idx] = to_tf32(w[(o * IMC_ + cin) * 9 + kk]);
}

// ---------------- implicit-GEMM tf32 conv (3x3, pad 1), split-K partials ----------------
// A[m][k]: input pixel (cin, STRIDE*oh+ky-1, STRIDE*ow+kx-1), k=cin*9+ky*3+kx, m=oh*54+ow
// B[k][n]: g_w1s / g_w2p (tf32, row-major K x 256)
#define APAD 68
#define BPAD 132
template<int STRIDE, int IH, int IW, int CONV1, int KCHUNK>
__global__ __launch_bounds__(256) void k_convmma() {
    const float* __restrict__ src = CONV1 ? g_xcat : g_y1;
    const float* __restrict__ wt  = CONV1 ? g_w1s : g_w2p;
    float* __restrict__ part = (CONV1 ? g_c1part : g_c2part) + (size_t)blockIdx.z * IMC_ * OSP;

    __shared__ float As[2][16 * APAD];
    __shared__ float Bs[2][16 * BPAD];

    int tid = threadIdx.x;
    int m0 = blockIdx.x * 64;
    int n0 = blockIdx.y * 128;
    int kbase = blockIdx.z * KCHUNK;

    int lane = tid & 31;
    int g = lane >> 2, t4 = lane & 3;
    int wid = tid >> 5;
    int wm = (wid & 1) * 32;
    int wn = (wid >> 1) * 32;

    // A loader coords
    int ma = tid & 63;
    int kqa = tid >> 6;       // 0..3
    int m = m0 + ma;
    bool mv = m < OSP;
    int mq = mv ? m : 0;
    int oh = mq / OW1, ow = mq - oh * OW1;
    int ihb = STRIDE * oh - 1, iwb = STRIDE * ow - 1;

    // B loader coords
    int nb = (tid & 31) * 4;
    int kqb = tid >> 5;       // 0..7 -> rows kqb, kqb+8

    float acc[2][4][4];
#pragma unroll
    for (int i = 0; i < 2; i++)
#pragma unroll
        for (int j = 0; j < 4; j++)
#pragma unroll
            for (int q = 0; q < 4; q++) acc[i][j][q] = 0.f;

    // prologue tile 0
    {
#pragma unroll
        for (int i = 0; i < 4; i++) {
            int kg = kbase + kqa * 4 + i;
            int cin = kg / 9; int r = kg - cin * 9;
            int ky = r / 3, kx = r - ky * 3;
            int ih = ihb + ky, iw = iwb + kx;
            bool ok = mv && ih >= 0 && ih < IH && iw >= 0 && iw < IW;
            float v = ok ? src[(size_t)cin * (IH * IW) + ih * IW + iw] : 0.f;
            As[0][(kqa * 4 + i) * APAD + ma] = to_tf32(v);
        }
#pragma unroll
        for (int p = 0; p < 2; p++) {
            int kk = kqb + p * 8;
            *(float4*)&Bs[0][kk * BPAD + nb] = *(const float4*)(wt + (size_t)(kbase + kk) * 256 + n0 + nb);
        }
    }
    __syncthreads();

    const int NT = KCHUNK / 16;
    for (int kt = 0; kt < NT; kt++) {
        int buf = kt & 1;
        float pa[4];
        float4 pb[2];
        if (kt + 1 < NT) {
            int k0n = kbase + (kt + 1) * 16;
#pragma unroll
            for (int i = 0; i < 4; i++) {
                int kg = k0n + kqa * 4 + i;
                int cin = kg / 9; int r = kg - cin * 9;
                int ky = r / 3, kx = r - ky * 3;
                int ih = ihb + ky, iw = iwb + kx;
                bool ok = mv && ih >= 0 && ih < IH && iw >= 0 && iw < IW;
                pa[i] = ok ? src[(size_t)cin * (IH * IW) + ih * IW + iw] : 0.f;
            }
#pragma unroll
            for (int p = 0; p < 2; p++) {
                int kk = kqb + p * 8;
                pb[p] = *(const float4*)(wt + (size_t)(k0n + kk) * 256 + n0 + nb);
            }
        }
#pragma unroll
        for (int ks = 0; ks < 2; ks++) {
            int kk = ks * 8;
            uint32_t af[2][4], bf[4][2];
#pragma unroll
            for (int mf = 0; mf < 2; mf++) {
                int mm = wm + mf * 16 + g;
                af[mf][0] = __float_as_uint(As[buf][(kk + t4) * APAD + mm]);
                af[mf][1] = __float_as_uint(As[buf][(kk + t4) * APAD + mm + 8]);
                af[mf][2] = __float_as_uint(As[buf][(kk + t4 + 4) * APAD + mm]);
                af[mf][3] = __float_as_uint(As[buf][(kk + t4 + 4) * APAD + mm + 8]);
            }
#pragma unroll
            for (int nf = 0; nf < 4; nf++) {
                int nn = wn + nf * 8 + g;
                bf[nf][0] = __float_as_uint(Bs[buf][(kk + t4) * BPAD + nn]);
                bf[nf][1] = __float_as_uint(Bs[buf][(kk + t4 + 4) * BPAD + nn]);
            }
#pragma unroll
            for (int mf = 0; mf < 2; mf++)
#pragma unroll
                for (int nf = 0; nf < 4; nf++) {
                    asm volatile(
                        "mma.sync.aligned.m16n8k8.row.col.f32.tf32.tf32.f32 "
                        "{%0,%1,%2,%3}, {%4,%5,%6,%7}, {%8,%9}, {%0,%1,%2,%3};"
                        : "+f"(acc[mf][nf][0]), "+f"(acc[mf][nf][1]),
                          "+f"(acc[mf][nf][2]), "+f"(acc[mf][nf][3])
                        : "r"(af[mf][0]), "r"(af[mf][1]), "r"(af[mf][2]), "r"(af[mf][3]),
                          "r"(bf[nf][0]), "r"(bf[nf][1]));
                }
        }
        if (kt + 1 < NT) {
            int b2 = buf ^ 1;
#pragma unroll
            for (int i = 0; i < 4; i++)
                As[b2][(kqa * 4 + i) * APAD + ma] = to_tf32(pa[i]);
#pragma unroll
            for (int p = 0; p < 2; p++)
                *(float4*)&Bs[b2][(kqb + p * 8) * BPAD + nb] = pb[p];
        }
        __syncthreads();
    }

    // epilogue: partials [o][p]
#pragma unroll
    for (int mf = 0; mf < 2; mf++) {
        int mrow = m0 + wm + mf * 16 + g;
#pragma unroll
        for (int nf = 0; nf < 4; nf++) {
            int o = n0 + wn + nf * 8 + 2 * t4;
            if (mrow < OSP) {
                part[(size_t)o * OSP + mrow] = acc[mf][nf][0];
                part[(size_t)(o + 1) * OSP + mrow] = acc[mf][nf][1];
            }
            if (mrow + 8 < OSP) {
                part[(size_t)o * OSP + mrow + 8] = acc[mf][nf][2];
                part[(size_t)(o + 1) * OSP + mrow + 8] = acc[mf][nf][3];
            }
        }
    }
}

__global__ void k_c1red(const float* __restrict__ bg, const float* __restrict__ bb,
                        const float* __restrict__ bm, const float* __restrict__ bv) {
    int idx = blockIdx.x * 256 + threadIdx.x;
    if (idx >= IMC_ * OSP) return;
    int o = idx / OSP;
    float s = g_c1part[idx] + g_c1part[IMC_ * OSP + idx]
            + g_c1part[2 * IMC_ * OSP + idx] + g_c1part[3 * IMC_ * OSP + idx];
    float sc = bg[o] / sqrtf(bv[o] + 1e-5f);
    g_y1[idx] = fmaxf((s - bm[o]) * sc + bb[o], 0.f);
}

__global__ void k_c2red(const float* __restrict__ bg, const float* __restrict__ bb,
                        const float* __restrict__ bm, const float* __restrict__ bv,
                        float* __restrict__ out) {
    int idx = blockIdx.x * 256 + threadIdx.x;
    if (idx >= IMC_ * OSP) return;
    int o = idx / OSP;
    float s = g_c2part[idx] + g_c2part[IMC_ * OSP + idx];
    float sc = bg[o] / sqrtf(bv[o] + 1e-5f);
    out[idx] = fmaxf((s - bm[o]) * sc + bb[o], 0.f);
}

// ---------------- launch ----------------
extern "C" void kernel_launch(void* const* d_in, const int* in_sizes, int n_in,
                              void* d_out, int out_size) {
    (void)in_sizes; (void)n_in; (void)out_size;
    const float* f0 = (const float*)d_in[0];
    const float* f1 = (const float*)d_in[1];
    const float* f2 = (const float*)d_in[2];
    const float* f3 = (const float*)d_in[3];
    const float* f4 = (const float*)d_in[4];
    const float* calib = (const float*)d_in[5];
    const float* oftw  = (const float*)d_in[6];
    const float* oftb  = (const float*)d_in[7];
    const float* attw  = (const float*)d_in[8];
    const float* attb  = (const float*)d_in[9];
    const float* c1w   = (const float*)d_in[10];
    const float* b1g   = (const float*)d_in[11];
    const float* b1b   = (const float*)d_in[12];
    const float* b1m   = (const float*)d_in[13];
    const float* b1v   = (const float*)d_in[14];
    const float* c2w   = (const float*)d_in[15];
    const float* b2g   = (const float*)d_in[16];
    const float* b2b   = (const float*)d_in[17];
    const float* b2m   = (const float*)d_in[18];
    const float* b2v   = (const float*)d_in[19];
    float* out = (float*)d_out;

    k_bbox<<<(NZN + 255) / 256, 256>>>(calib);
    k_permwb<<<(5 * 256 * HC_ + 255) / 256, 256>>>(oftw);
    k_permw2<<<(IMC_ * 9 * IMC_ + 255) / 256, 256>>>(c2w);

    k_pgemm<<<dim3(320, 18), 256>>>(f0, f1, f2, f3, f4);

    k_prow<<<(428544 + 255) / 256, 256>>>();
    k_pcol<<<(1428480 + 255) / 256, 256>>>();
    k_gather<<<dim3(NCELL, 5), 256>>>(oftb);

    k_colmean<<<CATC, 256>>>();
    k_att<<<5, 256>>>(attw, attb);
    k_wscale<<<(CATC * 9 * IMC_ + 255) / 256, 256>>>(c1w);

    // conv1: K = 1280*9 = 11520, split-K 4 (chunk 2880)
    k_convmma<2, NWC, ND, 1, 2880><<<dim3((OSP + 63) / 64, 2, 4), 256>>>();
    k_c1red<<<(IMC_ * OSP + 255) / 256, 256>>>(b1g, b1b, b1m, b1v);
    // conv2: K = 256*9 = 2304, split-K 2 (chunk 1152)
    k_convmma<1, OH1, OW1, 0, 1152><<<dim3((OSP + 63) / 64, 2, 2), 256>>>();
    k_c2red<<<(IMC_ * OSP + 255) / 256, 256>>>(b2g, b2b, b2m, b2v, out);
}

// round 6
// speedup vs baseline: 7.0760x; 1.1360x over previous
#include <cuda_runtime.h>
#include <cstdint>

// ---------------- problem constants ----------------
#define NZ 9
#define ND 108          // depth cells (conv W dim)
#define NWC 124         // width cells (conv H dim)
#define NCELL 13392     // ND*NWC
#define IMC_ 256
#define HC_ 2304        // 9*256
#define CATC 1280
#define OH1 62
#define OW1 54
#define OSP 3348        // 62*54

// level geometry
__device__ __constant__ int c_HH[5] = { 96, 48, 24, 12, 6 };
__device__ __constant__ int c_WW[5] = { 320, 160, 80, 40, 20 };
// float-offsets of per-level P buffers (HW*2304)
__device__ __constant__ int c_POFF[5]  = { 0, 70778880, 88473600, 92897280, 94003200 };
// cumulative M-tile (128) counts per level for the fused GEMM
__device__ __constant__ int c_MTCUM[6] = { 0, 240, 300, 315, 319, 320 };
// cumulative thread counts for merged cumsum kernels
__device__ __constant__ int c_RCUM[6] = { 0, 221184, 331776, 387072, 414720, 428544 };
__device__ __constant__ int c_CCUM[6] = { 0, 737280, 1105920, 1290240, 1382400, 1428480 };

// ---------------- scratch (device globals; no allocs allowed) ----------------
__device__ __align__(16) float g_P[94279680];       // all 5 levels, [z][hw][256] projected maps -> integral
__device__ __align__(16) float g_bbx[NCELL * 2];    // per-cell x bounds (z-independent)
__device__ __align__(16) float g_rtab[5 * NZ * ND * 12];  // row-tap table: rw[4], ro[4], yh, pad
__device__ __align__(16) float g_wb[5 * 256 * HC_];   // [l][c][z*256+o] tf32-rounded weights
__device__ __align__(16) float g_xcat[CATC * NCELL];  // concat ortho [1280][124][108]
__device__ __align__(16) float g_w1s[CATC * 9 * IMC_]; // [k=cin*9+kk][o], tf32, attention-folded
__device__ __align__(16) float g_w2p[IMC_ * 9 * IMC_]; // [k][o], tf32
__device__ float g_colmean[CATC];
__device__ float g_sig[CATC];
__device__ __align__(16) float g_y1[IMC_ * OSP];
__device__ __align__(16) float g_c1part[4 * IMC_ * OSP];
__device__ __align__(16) float g_c2part[2 * IMC_ * OSP];

__device__ __forceinline__ float to_tf32(float x) {
    float r;
    asm("cvt.rna.tf32.f32 %0, %1;" : "=f"(r) : "f"(x));
    return r;
}

// ---------------- corner projection (normalized, clamped) ----------------
__device__ __forceinline__ float2 projnc(const float* __restrict__ P, int zi, int di, int wi) {
    float X = 0.64f * (float)di;
    float Y = 39.68f - 0.64f * (float)wi;
    float Z = 2.76f - 0.64f * (float)zi;
    float hx = P[0] * X + P[1] * Y + P[2]  * Z + P[3];
    float hy = P[4] * X + P[5] * Y + P[6]  * Z + P[7];
    float hz = P[8] * X + P[9] * Y + P[10] * Z + P[11];
    float ix = hx / hz, iy = hy / hz;
    float nx = fminf(fmaxf(2.0f * ix / 1280.0f - 1.0f, -1.0f), 1.0f);
    float ny = fminf(fmaxf(2.0f * iy / 384.0f  - 1.0f, -1.0f), 1.0f);
    return make_float2(nx, ny);
}

// ---------------- per-cell x bounds (x is z-independent for this calib) ----------------
__global__ void k_bbx(const float* __restrict__ P) {
    int n = blockIdx.x * 256 + threadIdx.x;
    if (n >= NCELL) return;
    int d = n / NWC, w = n - d * NWC;
    float xa = projnc(P, 0, d,     w).x;
    float xb = projnc(P, 0, d + 1, w).x;
    float xc = projnc(P, 0, d + 1, w + 1).x;
    float xd = projnc(P, 0, d,     w + 1).x;
    g_bbx[n * 2 + 0] = fminf(xa, xb);
    g_bbx[n * 2 + 1] = fmaxf(xc, xd);
}

// ---------------- row-tap table per (l,z,d) (y is w-independent for this calib) ----------------
__global__ void k_rtab(const float* __restrict__ P) {
    int idx = blockIdx.x * 256 + threadIdx.x;
    if (idx >= 5 * NZ * ND) return;
    int d = idx % ND;
    int t = idx / ND;
    int z = t % NZ;
    int l = t / NZ;
    int Hf = c_HH[l], Wf = c_WW[l];

    float ya = projnc(P, z,     d,     0).y;
    float yb = projnc(P, z,     d + 1, 0).y;
    float yc = projnc(P, z + 1, d,     0).y;
    float yd = projnc(P, z + 1, d + 1, 0).y;
    float y1 = fminf(ya, yb);
    float y2 = fmaxf(yc, yd);

    float rw[4]; int ro[4];
    float ys[2] = { y1, y2 };
#pragma unroll
    for (int s = 0; s < 2; s++) {
        float y = (ys[s] + 1.f) * (Hf * 0.5f) - 0.5f;
        float yf = floorf(y);
        float wy = y - yf;
        int yi = (int)yf;
        float sg = s ? -1.f : 1.f;
        bool ok0 = (yi >= 0) && (yi < Hf);
        bool ok1 = (yi + 1 >= 0) && (yi + 1 < Hf);
        rw[s * 2 + 0] = ok0 ? sg * (1.f - wy) : 0.f;
        rw[s * 2 + 1] = ok1 ? sg * wy : 0.f;
        ro[s * 2 + 0] = ok0 ? yi * Wf * 256 : 0;
        ro[s * 2 + 1] = ok1 ? (yi + 1) * Wf * 256 : 0;
    }
    float* dst = g_rtab + (size_t)idx * 12;
    dst[0] = rw[0]; dst[1] = rw[1]; dst[2] = rw[2]; dst[3] = rw[3];
    ((int*)dst)[4] = ro[0]; ((int*)dst)[5] = ro[1];
    ((int*)dst)[6] = ro[2]; ((int*)dst)[7] = ro[3];
    dst[8] = y2 - y1;
    dst[9] = 0.f; dst[10] = 0.f; dst[11] = 0.f;
}

// ---------------- permute oft_w: g_wb[l][c][z*256+o] = tf32(w[l][o][c*9+z]) ----------------
__global__ void k_permwb(const float* __restrict__ w) {
    int idx = blockIdx.x * 256 + threadIdx.x;
    if (idx >= 5 * 256 * HC_) return;
    int zo = idx % HC_;
    int t = idx / HC_;
    int c = t & 255;
    int l = t >> 8;
    int z = zo >> 8, o = zo & 255;
    g_wb[idx] = to_tf32(w[((size_t)(l * IMC_ + o)) * HC_ + c * 9 + z]);
}

// ---------------- tf32 tensor-core GEMM: P[z][hw][o] = feats[c][hw]·W[c][zo] ----------------
#define SPAD 136
__global__ __launch_bounds__(256) void k_pgemm(
    const float* __restrict__ f0, const float* __restrict__ f1,
    const float* __restrict__ f2, const float* __restrict__ f3,
    const float* __restrict__ f4) {
    int bx = blockIdx.x;
    int l = 0;
    while (bx >= c_MTCUM[l + 1]) l++;
    int mtile = bx - c_MTCUM[l];
    int HW = c_HH[l] * c_WW[l];
    const float* __restrict__ Ag = (l == 0) ? f0 : (l == 1) ? f1 : (l == 2) ? f2 : (l == 3) ? f3 : f4;
    const float* __restrict__ Bg = g_wb + (size_t)l * 256 * HC_;
    float* __restrict__ P = g_P + c_POFF[l];

    __shared__ float As[2][16 * SPAD];
    __shared__ float Bs[2][16 * SPAD];

    int tid = threadIdx.x;
    int m0 = mtile * 128;
    int n0 = blockIdx.y * 128;

    int lane = tid & 31;
    int g = lane >> 2, t = lane & 3;
    int wid = tid >> 5;
    int wm = (wid & 1) * 64;
    int wn = (wid >> 1) * 32;

    float acc[4][4][4];
#pragma unroll
    for (int i = 0; i < 4; i++)
#pragma unroll
        for (int j = 0; j < 4; j++)
#pragma unroll
            for (int q = 0; q < 4; q++) acc[i][j][q] = 0.f;

    int ka0 = tid >> 5, ma0 = (tid & 31) * 4;
    int ka1 = (tid + 256) >> 5, ma1 = ma0;

    {
        float4 a0 = make_float4(0, 0, 0, 0), a1 = make_float4(0, 0, 0, 0);
        int gm0 = m0 + ma0, gm1 = m0 + ma1;
        if (gm0 < HW) a0 = *(const float4*)(Ag + (size_t)ka0 * HW + gm0);
        if (gm1 < HW) a1 = *(const float4*)(Ag + (size_t)ka1 * HW + gm1);
        float4 b0 = *(const float4*)(Bg + (size_t)ka0 * HC_ + n0 + ma0);
        float4 b1 = *(const float4*)(Bg + (size_t)ka1 * HC_ + n0 + ma1);
        As[0][ka0 * SPAD + ma0 + 0] = to_tf32(a0.x); As[0][ka0 * SPAD + ma0 + 1] = to_tf32(a0.y);
        As[0][ka0 * SPAD + ma0 + 2] = to_tf32(a0.z); As[0][ka0 * SPAD + ma0 + 3] = to_tf32(a0.w);
        As[0][ka1 * SPAD + ma1 + 0] = to_tf32(a1.x); As[0][ka1 * SPAD + ma1 + 1] = to_tf32(a1.y);
        As[0][ka1 * SPAD + ma1 + 2] = to_tf32(a1.z); As[0][ka1 * SPAD + ma1 + 3] = to_tf32(a1.w);
        *(float4*)&Bs[0][ka0 * SPAD + ma0] = b0;
        *(float4*)&Bs[0][ka1 * SPAD + ma1] = b1;
    }
    __syncthreads();

    const int NKT = 16;
    for (int kt = 0; kt < NKT; kt++) {
        int buf = kt & 1;
        float4 pa0 = make_float4(0, 0, 0, 0), pa1 = make_float4(0, 0, 0, 0);
        float4 pb0 = make_float4(0, 0, 0, 0), pb1 = make_float4(0, 0, 0, 0);
        if (kt + 1 < NKT) {
            int c0 = (kt + 1) * 16;
            int gm0 = m0 + ma0, gm1 = m0 + ma1;
            if (gm0 < HW) pa0 = *(const float4*)(Ag + (size_t)(c0 + ka0) * HW + gm0);
            if (gm1 < HW) pa1 = *(const float4*)(Ag + (size_t)(c0 + ka1) * HW + gm1);
            pb0 = *(const float4*)(Bg + (size_t)(c0 + ka0) * HC_ + n0 + ma0);
            pb1 = *(const float4*)(Bg + (size_t)(c0 + ka1) * HC_ + n0 + ma1);
        }
#pragma unroll
        for (int ks = 0; ks < 2; ks++) {
            int kk = ks * 8;
            uint32_t af[4][4], bf[4][2];
#pragma unroll
            for (int mf = 0; mf < 4; mf++) {
                int m = wm + mf * 16 + g;
                af[mf][0] = __float_as_uint(As[buf][(kk + t) * SPAD + m]);
                af[mf][1] = __float_as_uint(As[buf][(kk + t) * SPAD + m + 8]);
                af[mf][2] = __float_as_uint(As[buf][(kk + t + 4) * SPAD + m]);
                af[mf][3] = __float_as_uint(As[buf][(kk + t + 4) * SPAD + m + 8]);
            }
#pragma unroll
            for (int nf = 0; nf < 4; nf++) {
                int n = wn + nf * 8 + g;
                bf[nf][0] = __float_as_uint(Bs[buf][(kk + t) * SPAD + n]);
                bf[nf][1] = __float_as_uint(Bs[buf][(kk + t + 4) * SPAD + n]);
            }
#pragma unroll
            for (int mf = 0; mf < 4; mf++)
#pragma unroll
                for (int nf = 0; nf < 4; nf++) {
                    asm volatile(
                        "mma.sync.aligned.m16n8k8.row.col.f32.tf32.tf32.f32 "
                        "{%0,%1,%2,%3}, {%4,%5,%6,%7}, {%8,%9}, {%0,%1,%2,%3};"
                        : "+f"(acc[mf][nf][0]), "+f"(acc[mf][nf][1]),
                          "+f"(acc[mf][nf][2]), "+f"(acc[mf][nf][3])
                        : "r"(af[mf][0]), "r"(af[mf][1]), "r"(af[mf][2]), "r"(af[mf][3]),
                          "r"(bf[nf][0]), "r"(bf[nf][1]));
                }
        }
        if (kt + 1 < NKT) {
            int nb = buf ^ 1;
            As[nb][ka0 * SPAD + ma0 + 0] = to_tf32(pa0.x); As[nb][ka0 * SPAD + ma0 + 1] = to_tf32(pa0.y);
            As[nb][ka0 * SPAD + ma0 + 2] = to_tf32(pa0.z); As[nb][ka0 * SPAD + ma0 + 3] = to_tf32(pa0.w);
            As[nb][ka1 * SPAD + ma1 + 0] = to_tf32(pa1.x); As[nb][ka1 * SPAD + ma1 + 1] = to_tf32(pa1.y);
            As[nb][ka1 * SPAD + ma1 + 2] = to_tf32(pa1.z); As[nb][ka1 * SPAD + ma1 + 3] = to_tf32(pa1.w);
            *(float4*)&Bs[nb][ka0 * SPAD + ma0] = pb0;
            *(float4*)&Bs[nb][ka1 * SPAD + ma1] = pb1;
        }
        __syncthreads();
    }

    int z = n0 >> 8;
    int ob0 = n0 & 255;
#pragma unroll
    for (int mf = 0; mf < 4; mf++) {
        int m = m0 + wm + mf * 16 + g;
#pragma unroll
        for (int nf = 0; nf < 4; nf++) {
            int o = ob0 + wn + nf * 8 + 2 * t;
            if (m < HW) {
                float* dst = P + ((size_t)z * HW + m) * 256 + o;
                *(float2*)dst = make_float2(acc[mf][nf][0], acc[mf][nf][1]);
            }
            if (m + 8 < HW) {
                float* dst = P + ((size_t)z * HW + m + 8) * 256 + o;
                *(float2*)dst = make_float2(acc[mf][nf][2], acc[mf][nf][3]);
            }
        }
    }
}

// ---------------- merged cumsum of P along w (all levels) ----------------
__global__ void k_prow(void) {
    int t = blockIdx.x * 256 + threadIdx.x;
    if (t >= 428544) return;
    int l = 0;
    while (t >= c_RCUM[l + 1]) l++;
    int tt = t - c_RCUM[l];
    int H = c_HH[l], W = c_WW[l];
    int o = tt & 255;
    int r = tt >> 8;
    int h = r % H, z = r / H;
    float* p = g_P + c_POFF[l] + ((size_t)(z * H + h) * W) * 256 + o;
    float a = 0.f;
    for (int w = 0; w < W; w++) { int off = w * 256; a += p[off]; p[off] = a; }
}

// ---------------- merged cumsum of P along h (all levels) ----------------
__global__ void k_pcol(void) {
    int t = blockIdx.x * 256 + threadIdx.x;
    if (t >= 1428480) return;
    int l = 0;
    while (t >= c_CCUM[l + 1]) l++;
    int tt = t - c_CCUM[l];
    int H = c_HH[l], W = c_WW[l];
    int o = tt & 255;
    int r = tt >> 8;
    int w = r % W, z = r / W;
    float* p = g_P + c_POFF[l] + ((size_t)z * H * W + w) * 256 + o;
    float a = 0.f;
    int stride = W * 256;
    for (int h = 0; h < H; h++) { int off = h * stride; a += p[off]; p[off] = a; }
}

// ---------------- fused gather (table-driven): ortho[n][o] = relu(b + sum_z taps) ----------------
__global__ __launch_bounds__(256) void k_gather(const float* __restrict__ bias) {
    int n = blockIdx.x;
    int l = blockIdx.y;
    int o = threadIdx.x;
    int Hf = c_HH[l], Wf = c_WW[l];
    int HW = Hf * Wf;
    float areaF = (float)HW * 0.25f;
    const float* __restrict__ P = g_P + c_POFF[l];
    int d = n / NWC;

    float2 bx = *(const float2*)&g_bbx[n * 2];
    float xw = bx.y - bx.x;
    float acc = bias[l * 256 + o];

    // column taps (shared across all z)
    float cw0, cw1, cw2, cw3; int co0, co1, co2, co3;
    {
        float x = (bx.x + 1.f) * (Wf * 0.5f) - 0.5f;
        float xf = floorf(x); float wx = x - xf; int xi = (int)xf;
        bool ok0 = (xi >= 0) && (xi < Wf);
        bool ok1 = (xi + 1 >= 0) && (xi + 1 < Wf);
        cw0 = ok0 ? (1.f - wx) : 0.f;  co0 = ok0 ? xi * 256 : 0;
        cw1 = ok1 ? wx : 0.f;          co1 = ok1 ? (xi + 1) * 256 : 0;
    }
    {
        float x = (bx.y + 1.f) * (Wf * 0.5f) - 0.5f;
        float xf = floorf(x); float wx = x - xf; int xi = (int)xf;
        bool ok0 = (xi >= 0) && (xi < Wf);
        bool ok1 = (xi + 1 >= 0) && (xi + 1 < Wf);
        cw2 = ok0 ? -(1.f - wx) : 0.f; co2 = ok0 ? xi * 256 : 0;
        cw3 = ok1 ? -wx : 0.f;         co3 = ok1 ? (xi + 1) * 256 : 0;
    }

    const float* tab = g_rtab + (size_t)((l * NZ) * ND + d) * 12;
#pragma unroll
    for (int z = 0; z < NZ; z++, tab += ND * 12) {
        float4 rw = *(const float4*)tab;
        int4 ro = *(const int4*)(tab + 4);
        float yh = tab[8];
        float area = xw * yh * areaF + 1e-6f;
        if (!(area > 1e-6f)) continue;
        float inv = 1.0f / area;
        const float* Pz = P + (size_t)z * HW * 256 + o;
        {
            const float* Pr = Pz + ro.x;
            float rs = cw0 * Pr[co0] + cw1 * Pr[co1] + cw2 * Pr[co2] + cw3 * Pr[co3];
            acc += (rw.x * inv) * rs;
        }
        {
            const float* Pr = Pz + ro.y;
            float rs = cw0 * Pr[co0] + cw1 * Pr[co1] + cw2 * Pr[co2] + cw3 * Pr[co3];
            acc += (rw.y * inv) * rs;
        }
        {
            const float* Pr = Pz + ro.z;
            float rs = cw0 * Pr[co0] + cw1 * Pr[co1] + cw2 * Pr[co2] + cw3 * Pr[co3];
            acc += (rw.z * inv) * rs;
        }
        {
            const float* Pr = Pz + ro.w;
            float rs = cw0 * Pr[co0] + cw1 * Pr[co1] + cw2 * Pr[co2] + cw3 * Pr[co3];
            acc += (rw.w * inv) * rs;
        }
    }
    int dd = n / NWC, w = n - dd * NWC;
    int sp = w * ND + dd;
    g_xcat[(l * 256 + o) * NCELL + sp] = fmaxf(acc, 0.0f);
}

// ---------------- channel means ----------------
__global__ void k_colmean() {
    int g = blockIdx.x;
    const float* p = g_xcat + g * NCELL;
    float s = 0.f;
    for (int i = threadIdx.x; i < NCELL; i += 256) s += p[i];
    __shared__ float sm[256];
    sm[threadIdx.x] = s;
    __syncthreads();
    for (int st = 128; st > 0; st >>= 1) {
        if (threadIdx.x < st) sm[threadIdx.x] += sm[threadIdx.x + st];
        __syncthreads();
    }
    if (threadIdx.x == 0) g_colmean[g] = sm[0] * (1.0f / (float)NCELL);
}

__global__ void k_att(const float* __restrict__ aw, const float* __restrict__ ab) {
    __shared__ float cm[IMC_];
    int l = blockIdx.x, o = threadIdx.x;
    cm[o] = g_colmean[l * IMC_ + o];
    __syncthreads();
    float acc = ab[o];
    for (int c = 0; c < IMC_; c++) acc += cm[c] * aw[o * IMC_ + c];
    g_sig[l * IMC_ + o] = 1.0f / (1.0f + expf(-acc));
}

// ---------------- fold attention + transpose conv1 weights -> tf32 [k][o] ----------------
__global__ void k_wscale(const float* __restrict__ w) {
    int idx = blockIdx.x * 256 + threadIdx.x;
    if (idx >= CATC * 9 * IMC_) return;
    int o = idx & 255;
    int t = idx >> 8;
    int kk = t % 9;
    int cin = t / 9;
    g_w1s[idx] = to_tf32(w[(o * CATC + cin) * 9 + kk] * g_sig[cin]);
}

__global__ void k_permw2(const float* __restrict__ w) {
    int idx = blockIdx.x * 256 + threadIdx.x;
    if (idx >= IMC_ * 9 * IMC_) return;
    int o = idx & 255;
    int t = idx >> 8;
    int kk = t % 9;
    int cin = t / 9;
    g_w2p[idx] = to_tf32(w[(o * IMC_ + cin) * 9 + kk]);
}

// ---------------- implicit-GEMM tf32 conv (3x3, pad 1), split-K partials ----------------
#define APAD 68
#define BPAD 132
template<int STRIDE, int IH, int IW, int CONV1, int KCHUNK>
__global__ __launch_bounds__(256) void k_convmma() {
    const float* __restrict__ src = CONV1 ? g_xcat : g_y1;
    const float* __restrict__ wt  = CONV1 ? g_w1s : g_w2p;
    float* __restrict__ part = (CONV1 ? g_c1part : g_c2part) + (size_t)blockIdx.z * IMC_ * OSP;

    __shared__ float As[2][16 * APAD];
    __shared__ float Bs[2][16 * BPAD];

    int tid = threadIdx.x;
    int m0 = blockIdx.x * 64;
    int n0 = blockIdx.y * 128;
    int kbase = blockIdx.z * KCHUNK;

    int lane = tid & 31;
    int g = lane >> 2, t4 = lane & 3;
    int wid = tid >> 5;
    int wm = (wid & 1) * 32;
    int wn = (wid >> 1) * 32;

    int ma = tid & 63;
    int kqa = tid >> 6;
    int m = m0 + ma;
    bool mv = m < OSP;
    int mq = mv ? m : 0;
    int oh = mq / OW1, ow = mq - oh * OW1;
    int ihb = STRIDE * oh - 1, iwb = STRIDE * ow - 1;

    int nb = (tid & 31) * 4;
    int kqb = tid >> 5;

    float acc[2][4][4];
#pragma unroll
    for (int i = 0; i < 2; i++)
#pragma unroll
        for (int j = 0; j < 4; j++)
#pragma unroll
            for (int q = 0; q < 4; q++) acc[i][j][q] = 0.f;

    {
#pragma unroll
        for (int i = 0; i < 4; i++) {
            int kg = kbase + kqa * 4 + i;
            int cin = kg / 9; int r = kg - cin * 9;
            int ky = r / 3, kx = r - ky * 3;
            int ih = ihb + ky, iw = iwb + kx;
            bool ok = mv && ih >= 0 && ih < IH && iw >= 0 && iw < IW;
            float v = ok ? src[(size_t)cin * (IH * IW) + ih * IW + iw] : 0.f;
            As[0][(kqa * 4 + i) * APAD + ma] = to_tf32(v);
        }
#pragma unroll
        for (int p = 0; p < 2; p++) {
            int kk = kqb + p * 8;
            *(float4*)&Bs[0][kk * BPAD + nb] = *(const float4*)(wt + (size_t)(kbase + kk) * 256 + n0 + nb);
        }
    }
    __syncthreads();

    const int NT = KCHUNK / 16;
    for (int kt = 0; kt < NT; kt++) {
        int buf = kt & 1;
        float pa[4];
        float4 pb[2];
        if (kt + 1 < NT) {
            int k0n = kbase + (kt + 1) * 16;
#pragma unroll
            for (int i = 0; i < 4; i++) {
                int kg = k0n + kqa * 4 + i;
                int cin = kg / 9; int r = kg - cin * 9;
                int ky = r / 3, kx = r - ky * 3;
                int ih = ihb + ky, iw = iwb + kx;
                bool ok = mv && ih >= 0 && ih < IH && iw >= 0 && iw < IW;
                pa[i] = ok ? src[(size_t)cin * (IH * IW) + ih * IW + iw] : 0.f;
            }
#pragma unroll
            for (int p = 0; p < 2; p++) {
                int kk = kqb + p * 8;
                pb[p] = *(const float4*)(wt + (size_t)(k0n + kk) * 256 + n0 + nb);
            }
        }
#pragma unroll
        for (int ks = 0; ks < 2; ks++) {
            int kk = ks * 8;
            uint32_t af[2][4], bf[4][2];
#pragma unroll
            for (int mf = 0; mf < 2; mf++) {
                int mm = wm + mf * 16 + g;
                af[mf][0] = __float_as_uint(As[buf][(kk + t4) * APAD + mm]);
                af[mf][1] = __float_as_uint(As[buf][(kk + t4) * APAD + mm + 8]);
                af[mf][2] = __float_as_uint(As[buf][(kk + t4 + 4) * APAD + mm]);
                af[mf][3] = __float_as_uint(As[buf][(kk + t4 + 4) * APAD + mm + 8]);
            }
#pragma unroll
            for (int nf = 0; nf < 4; nf++) {
                int nn = wn + nf * 8 + g;
                bf[nf][0] = __float_as_uint(Bs[buf][(kk + t4) * BPAD + nn]);
                bf[nf][1] = __float_as_uint(Bs[buf][(kk + t4 + 4) * BPAD + nn]);
            }
#pragma unroll
            for (int mf = 0; mf < 2; mf++)
#pragma unroll
                for (int nf = 0; nf < 4; nf++) {
                    asm volatile(
                        "mma.sync.aligned.m16n8k8.row.col.f32.tf32.tf32.f32 "
                        "{%0,%1,%2,%3}, {%4,%5,%6,%7}, {%8,%9}, {%0,%1,%2,%3};"
                        : "+f"(acc[mf][nf][0]), "+f"(acc[mf][nf][1]),
                          "+f"(acc[mf][nf][2]), "+f"(acc[mf][nf][3])
                        : "r"(af[mf][0]), "r"(af[mf][1]), "r"(af[mf][2]), "r"(af[mf][3]),
                          "r"(bf[nf][0]), "r"(bf[nf][1]));
                }
        }
        if (kt + 1 < NT) {
            int b2 = buf ^ 1;
#pragma unroll
            for (int i = 0; i < 4; i++)
                As[b2][(kqa * 4 + i) * APAD + ma] = to_tf32(pa[i]);
#pragma unroll
            for (int p = 0; p < 2; p++)
                *(float4*)&Bs[b2][(kqb + p * 8) * BPAD + nb] = pb[p];
        }
        __syncthreads();
    }

#pragma unroll
    for (int mf = 0; mf < 2; mf++) {
        int mrow = m0 + wm + mf * 16 + g;
#pragma unroll
        for (int nf = 0; nf < 4; nf++) {
            int o = n0 + wn + nf * 8 + 2 * t4;
            if (mrow < OSP) {
                part[(size_t)o * OSP + mrow] = acc[mf][nf][0];
                part[(size_t)(o + 1) * OSP + mrow] = acc[mf][nf][1];
            }
            if (mrow + 8 < OSP) {
                part[(size_t)o * OSP + mrow + 8] = acc[mf][nf][2];
                part[(size_t)(o + 1) * OSP + mrow + 8] = acc[mf][nf][3];
            }
        }
    }
}

__global__ void k_c1red(const float* __restrict__ bg, const float* __restrict__ bb,
                        const float* __restrict__ bm, const float* __restrict__ bv) {
    int idx = blockIdx.x * 256 + threadIdx.x;
    if (idx >= IMC_ * OSP) return;
    int o = idx / OSP;
    float s = g_c1part[idx] + g_c1part[IMC_ * OSP + idx]
            + g_c1part[2 * IMC_ * OSP + idx] + g_c1part[3 * IMC_ * OSP + idx];
    float sc = bg[o] / sqrtf(bv[o] + 1e-5f);
    g_y1[idx] = fmaxf((s - bm[o]) * sc + bb[o], 0.f);
}

__global__ void k_c2red(const float* __restrict__ bg, const float* __restrict__ bb,
                        const float* __restrict__ bm, const float* __restrict__ bv,
                        float* __restrict__ out) {
    int idx = blockIdx.x * 256 + threadIdx.x;
    if (idx >= IMC_ * OSP) return;
    int o = idx / OSP;
    float s = g_c2part[idx] + g_c2part[IMC_ * OSP + idx];
    float sc = bg[o] / sqrtf(bv[o] + 1e-5f);
    out[idx] = fmaxf((s - bm[o]) * sc + bb[o], 0.f);
}

// ---------------- launch ----------------
extern "C" void kernel_launch(void* const* d_in, const int* in_sizes, int n_in,
                              void* d_out, int out_size) {
    (void)in_sizes; (void)n_in; (void)out_size;
    const float* f0 = (const float*)d_in[0];
    const float* f1 = (const float*)d_in[1];
    const float* f2 = (const float*)d_in[2];
    const float* f3 = (const float*)d_in[3];
    const float* f4 = (const float*)d_in[4];
    const float* calib = (const float*)d_in[5];
    const float* oftw  = (const float*)d_in[6];
    const float* oftb  = (const float*)d_in[7];
    const float* attw  = (const float*)d_in[8];
    const float* attb  = (const float*)d_in[9];
    const float* c1w   = (const float*)d_in[10];
    const float* b1g   = (const float*)d_in[11];
    const float* b1b   = (const float*)d_in[12];
    const float* b1m   = (const float*)d_in[13];
    const float* b1v   = (const float*)d_in[14];
    const float* c2w   = (const float*)d_in[15];
    const float* b2g   = (const float*)d_in[16];
    const float* b2b   = (const float*)d_in[17];
    const float* b2m   = (const float*)d_in[18];
    const float* b2v   = (const float*)d_in[19];
    float* out = (float*)d_out;

    k_bbx<<<(NCELL + 255) / 256, 256>>>(calib);
    k_rtab<<<(5 * NZ * ND + 255) / 256, 256>>>(calib);
    k_permwb<<<(5 * 256 * HC_ + 255) / 256, 256>>>(oftw);
    k_permw2<<<(IMC_ * 9 * IMC_ + 255) / 256, 256>>>(c2w);

    k_pgemm<<<dim3(320, 18), 256>>>(f0, f1, f2, f3, f4);

    k_prow<<<(428544 + 255) / 256, 256>>>();
    k_pcol<<<(1428480 + 255) / 256, 256>>>();
    k_gather<<<dim3(NCELL, 5), 256>>>(oftb);

    k_colmean<<<CATC, 256>>>();
    k_att<<<5, 256>>>(attw, attb);
    k_wscale<<<(CATC * 9 * IMC_ + 255) / 256, 256>>>(c1w);

    // conv1: K = 1280*9 = 11520, split-K 4 (chunk 2880)
    k_convmma<2, NWC, ND, 1, 2880><<<dim3((OSP + 63) / 64, 2, 4), 256>>>();
    k_c1red<<<(IMC_ * OSP + 255) / 256, 256>>>(b1g, b1b, b1m, b1v);
    // conv2: K = 256*9 = 2304, split-K 2 (chunk 1152)
    k_convmma<1, OH1, OW1, 0, 1152><<<dim3((OSP + 63) / 64, 2, 2), 256>>>();
    k_c2red<<<(IMC_ * OSP + 255) / 256, 256>>>(b2g, b2b, b2m, b2v, out);
}

// round 7
// speedup vs baseline: 7.5714x; 1.0700x over previous
#include <cuda_runtime.h>
#include <cstdint>

// ---------------- problem constants ----------------
#define NZ 9
#define ND 108          // depth cells (conv W dim)
#define NWC 124         // width cells (conv H dim)
#define NCELL 13392     // ND*NWC
#define IMC_ 256
#define HC_ 2304        // 9*256
#define CATC 1280
#define OH1 62
#define OW1 54
#define OSP 3348        // 62*54

// level geometry
__device__ __constant__ int c_HH[5] = { 96, 48, 24, 12, 6 };
__device__ __constant__ int c_WW[5] = { 320, 160, 80, 40, 20 };
// float-offsets of per-level P buffers (HW*2304)
__device__ __constant__ int c_POFF[5]  = { 0, 70778880, 88473600, 92897280, 94003200 };
// cumulative M-tile (128) counts per level for the fused GEMM
__device__ __constant__ int c_MTCUM[6] = { 0, 240, 300, 315, 319, 320 };
// cumulative thread counts for merged float4 cumsum kernels
__device__ __constant__ int c_RCUM4[6] = { 0, 55296, 82944, 96768, 103680, 107136 };
__device__ __constant__ int c_CCUM4[6] = { 0, 184320, 276480, 322560, 345600, 357120 };

// ---------------- scratch (device globals; no allocs allowed) ----------------
__device__ __align__(16) float g_P[94279680];       // all 5 levels, [z][hw][256] projected maps -> integral
__device__ __align__(16) float g_ctab[5 * NCELL * 12];    // col-tap table per (l,n): cw[4], co[4], xw, ncol
__device__ __align__(16) float g_rtab[5 * NZ * ND * 12];  // row-tap table per (l,z,d): rw[4], ro[4], yh, nrow
__device__ __align__(16) float g_wb[5 * 256 * HC_];   // [l][c][z*256+o] tf32-rounded weights
__device__ __align__(16) float g_xcat[CATC * NCELL];  // concat ortho [1280][124][108]
__device__ __align__(16) float g_w1s[CATC * 9 * IMC_]; // [k=cin*9+kk][o], tf32, attention-folded
__device__ __align__(16) float g_w2p[IMC_ * 9 * IMC_]; // [k][o], tf32
__device__ float g_colmean[CATC];
__device__ float g_sig[CATC];
__device__ __align__(16) float g_y1[IMC_ * OSP];
__device__ __align__(16) float g_c1part[4 * IMC_ * OSP];
__device__ __align__(16) float g_c2part[2 * IMC_ * OSP];

__device__ __forceinline__ float to_tf32(float x) {
    float r;
    asm("cvt.rna.tf32.f32 %0, %1;" : "=f"(r) : "f"(x));
    return r;
}

// ---------------- corner projection (normalized, clamped) ----------------
__device__ __forceinline__ float2 projnc(const float* __restrict__ P, int zi, int di, int wi) {
    float X = 0.64f * (float)di;
    float Y = 39.68f - 0.64f * (float)wi;
    float Z = 2.76f - 0.64f * (float)zi;
    float hx = P[0] * X + P[1] * Y + P[2]  * Z + P[3];
    float hy = P[4] * X + P[5] * Y + P[6]  * Z + P[7];
    float hz = P[8] * X + P[9] * Y + P[10] * Z + P[11];
    float ix = hx / hz, iy = hy / hz;
    float nx = fminf(fmaxf(2.0f * ix / 1280.0f - 1.0f, -1.0f), 1.0f);
    float ny = fminf(fmaxf(2.0f * iy / 384.0f  - 1.0f, -1.0f), 1.0f);
    return make_float2(nx, ny);
}

// ---------------- col-tap table per (l,n): dedupe merged bilinear taps ----------------
__global__ void k_ctab(const float* __restrict__ P) {
    int idx = blockIdx.x * 256 + threadIdx.x;
    if (idx >= 5 * NCELL) return;
    int n = idx % NCELL;
    int l = idx / NCELL;
    int d = n / NWC, w = n - d * NWC;
    int Wf = c_WW[l];

    // x is z-independent for this calibration
    float xa = projnc(P, 0, d,     w).x;
    float xb = projnc(P, 0, d + 1, w).x;
    float xc = projnc(P, 0, d + 1, w + 1).x;
    float xd = projnc(P, 0, d,     w + 1).x;
    float x1 = fminf(xa, xb);
    float x2 = fmaxf(xc, xd);

    float xp1 = (x1 + 1.f) * (Wf * 0.5f) - 0.5f;
    float xf1 = floorf(xp1); float wx1 = xp1 - xf1; int xi1 = (int)xf1;
    float xp2 = (x2 + 1.f) * (Wf * 0.5f) - 0.5f;
    float xf2 = floorf(xp2); float wx2 = xp2 - xf2; int xi2 = (int)xf2;

    float cw[4]; int co[4]; int ncol;
    if (xi2 == xi1) {
        ncol = 2;
        co[0] = xi1;     cw[0] = wx2 - wx1;            // (1-wx1) - (1-wx2)
        co[1] = xi1 + 1; cw[1] = wx1 - wx2;
        co[2] = 0; cw[2] = 0.f; co[3] = 0; cw[3] = 0.f;
    } else if (xi2 == xi1 + 1) {
        ncol = 3;
        co[0] = xi1;     cw[0] = 1.f - wx1;
        co[1] = xi1 + 1; cw[1] = wx1 - (1.f - wx2);
        co[2] = xi2 + 1; cw[2] = -wx2;
        co[3] = 0; cw[3] = 0.f;
    } else {
        ncol = 4;
        co[0] = xi1;     cw[0] = 1.f - wx1;
        co[1] = xi1 + 1; cw[1] = wx1;
        co[2] = xi2;     cw[2] = -(1.f - wx2);
        co[3] = xi2 + 1; cw[3] = -wx2;
    }
#pragma unroll
    for (int i = 0; i < 4; i++) {
        bool ok = (co[i] >= 0) && (co[i] < Wf);
        cw[i] = ok ? cw[i] : 0.f;
        co[i] = ok ? co[i] * 256 : 0;
    }
    float* dst = g_ctab + (size_t)idx * 12;
    dst[0] = cw[0]; dst[1] = cw[1]; dst[2] = cw[2]; dst[3] = cw[3];
    ((int*)dst)[4] = co[0]; ((int*)dst)[5] = co[1];
    ((int*)dst)[6] = co[2]; ((int*)dst)[7] = co[3];
    dst[8] = x2 - x1;
    ((int*)dst)[9] = ncol;
    dst[10] = 0.f; dst[11] = 0.f;
}

// ---------------- row-tap table per (l,z,d): dedupe merged bilinear taps ----------------
__global__ void k_rtab(const float* __restrict__ P) {
    int idx = blockIdx.x * 256 + threadIdx.x;
    if (idx >= 5 * NZ * ND) return;
    int d = idx % ND;
    int t = idx / ND;
    int z = t % NZ;
    int l = t / NZ;
    int Hf = c_HH[l], Wf = c_WW[l];

    float ya = projnc(P, z,     d,     0).y;
    float yb = projnc(P, z,     d + 1, 0).y;
    float yc = projnc(P, z + 1, d,     0).y;
    float yd = projnc(P, z + 1, d + 1, 0).y;
    float y1 = fminf(ya, yb);
    float y2 = fmaxf(yc, yd);

    float yp1 = (y1 + 1.f) * (Hf * 0.5f) - 0.5f;
    float yf1 = floorf(yp1); float wy1 = yp1 - yf1; int yi1 = (int)yf1;
    float yp2 = (y2 + 1.f) * (Hf * 0.5f) - 0.5f;
    float yf2 = floorf(yp2); float wy2 = yp2 - yf2; int yi2 = (int)yf2;

    float rw[4]; int ro[4]; int nrow;
    if (yi2 == yi1) {
        nrow = 2;
        ro[0] = yi1;     rw[0] = wy2 - wy1;
        ro[1] = yi1 + 1; rw[1] = wy1 - wy2;
        ro[2] = 0; rw[2] = 0.f; ro[3] = 0; rw[3] = 0.f;
    } else if (yi2 == yi1 + 1) {
        nrow = 3;
        ro[0] = yi1;     rw[0] = 1.f - wy1;
        ro[1] = yi1 + 1; rw[1] = wy1 - (1.f - wy2);
        ro[2] = yi2 + 1; rw[2] = -wy2;
        ro[3] = 0; rw[3] = 0.f;
    } else {
        nrow = 4;
        ro[0] = yi1;     rw[0] = 1.f - wy1;
        ro[1] = yi1 + 1; rw[1] = wy1;
        ro[2] = yi2;     rw[2] = -(1.f - wy2);
        ro[3] = yi2 + 1; rw[3] = -wy2;
    }
#pragma unroll
    for (int i = 0; i < 4; i++) {
        bool ok = (ro[i] >= 0) && (ro[i] < Hf);
        rw[i] = ok ? rw[i] : 0.f;
        ro[i] = ok ? ro[i] * Wf * 256 : 0;
    }
    float* dst = g_rtab + (size_t)idx * 12;
    dst[0] = rw[0]; dst[1] = rw[1]; dst[2] = rw[2]; dst[3] = rw[3];
    ((int*)dst)[4] = ro[0]; ((int*)dst)[5] = ro[1];
    ((int*)dst)[6] = ro[2]; ((int*)dst)[7] = ro[3];
    dst[8] = y2 - y1;
    ((int*)dst)[9] = nrow;
    dst[10] = 0.f; dst[11] = 0.f;
}

// ---------------- permute oft_w: g_wb[l][c][z*256+o] = tf32(w[l][o][c*9+z]) ----------------
__global__ void k_permwb(const float* __restrict__ w) {
    int idx = blockIdx.x * 256 + threadIdx.x;
    if (idx >= 5 * 256 * HC_) return;
    int zo = idx % HC_;
    int t = idx / HC_;
    int c = t & 255;
    int l = t >> 8;
    int z = zo >> 8, o = zo & 255;
    g_wb[idx] = to_tf32(w[((size_t)(l * IMC_ + o)) * HC_ + c * 9 + z]);
}

// ---------------- tf32 tensor-core GEMM: P[z][hw][o] = feats[c][hw]·W[c][zo] ----------------
#define SPAD 136
__global__ __launch_bounds__(256) void k_pgemm(
    const float* __restrict__ f0, const float* __restrict__ f1,
    const float* __restrict__ f2, const float* __restrict__ f3,
    const float* __restrict__ f4) {
    int bx = blockIdx.x;
    int l = 0;
    while (bx >= c_MTCUM[l + 1]) l++;
    int mtile = bx - c_MTCUM[l];
    int HW = c_HH[l] * c_WW[l];
    const float* __restrict__ Ag = (l == 0) ? f0 : (l == 1) ? f1 : (l == 2) ? f2 : (l == 3) ? f3 : f4;
    const float* __restrict__ Bg = g_wb + (size_t)l * 256 * HC_;
    float* __restrict__ P = g_P + c_POFF[l];

    __shared__ float As[2][16 * SPAD];
    __shared__ float Bs[2][16 * SPAD];

    int tid = threadIdx.x;
    int m0 = mtile * 128;
    int n0 = blockIdx.y * 128;

    int lane = tid & 31;
    int g = lane >> 2, t = lane & 3;
    int wid = tid >> 5;
    int wm = (wid & 1) * 64;
    int wn = (wid >> 1) * 32;

    float acc[4][4][4];
#pragma unroll
    for (int i = 0; i < 4; i++)
#pragma unroll
        for (int j = 0; j < 4; j++)
#pragma unroll
            for (int q = 0; q < 4; q++) acc[i][j][q] = 0.f;

    int ka0 = tid >> 5, ma0 = (tid & 31) * 4;
    int ka1 = (tid + 256) >> 5, ma1 = ma0;

    {
        float4 a0 = make_float4(0, 0, 0, 0), a1 = make_float4(0, 0, 0, 0);
        int gm0 = m0 + ma0, gm1 = m0 + ma1;
        if (gm0 < HW) a0 = *(const float4*)(Ag + (size_t)ka0 * HW + gm0);
        if (gm1 < HW) a1 = *(const float4*)(Ag + (size_t)ka1 * HW + gm1);
        float4 b0 = *(const float4*)(Bg + (size_t)ka0 * HC_ + n0 + ma0);
        float4 b1 = *(const float4*)(Bg + (size_t)ka1 * HC_ + n0 + ma1);
        As[0][ka0 * SPAD + ma0 + 0] = to_tf32(a0.x); As[0][ka0 * SPAD + ma0 + 1] = to_tf32(a0.y);
        As[0][ka0 * SPAD + ma0 + 2] = to_tf32(a0.z); As[0][ka0 * SPAD + ma0 + 3] = to_tf32(a0.w);
        As[0][ka1 * SPAD + ma1 + 0] = to_tf32(a1.x); As[0][ka1 * SPAD + ma1 + 1] = to_tf32(a1.y);
        As[0][ka1 * SPAD + ma1 + 2] = to_tf32(a1.z); As[0][ka1 * SPAD + ma1 + 3] = to_tf32(a1.w);
        *(float4*)&Bs[0][ka0 * SPAD + ma0] = b0;
        *(float4*)&Bs[0][ka1 * SPAD + ma1] = b1;
    }
    __syncthreads();

    const int NKT = 16;
    for (int kt = 0; kt < NKT; kt++) {
        int buf = kt & 1;
        float4 pa0 = make_float4(0, 0, 0, 0), pa1 = make_float4(0, 0, 0, 0);
        float4 pb0 = make_float4(0, 0, 0, 0), pb1 = make_float4(0, 0, 0, 0);
        if (kt + 1 < NKT) {
            int c0 = (kt + 1) * 16;
            int gm0 = m0 + ma0, gm1 = m0 + ma1;
            if (gm0 < HW) pa0 = *(const float4*)(Ag + (size_t)(c0 + ka0) * HW + gm0);
            if (gm1 < HW) pa1 = *(const float4*)(Ag + (size_t)(c0 + ka1) * HW + gm1);
            pb0 = *(const float4*)(Bg + (size_t)(c0 + ka0) * HC_ + n0 + ma0);
            pb1 = *(const float4*)(Bg + (size_t)(c0 + ka1) * HC_ + n0 + ma1);
        }
#pragma unroll
        for (int ks = 0; ks < 2; ks++) {
            int kk = ks * 8;
            uint32_t af[4][4], bf[4][2];
#pragma unroll
            for (int mf = 0; mf < 4; mf++) {
                int m = wm + mf * 16 + g;
                af[mf][0] = __float_as_uint(As[buf][(kk + t) * SPAD + m]);
                af[mf][1] = __float_as_uint(As[buf][(kk + t) * SPAD + m + 8]);
                af[mf][2] = __float_as_uint(As[buf][(kk + t + 4) * SPAD + m]);
                af[mf][3] = __float_as_uint(As[buf][(kk + t + 4) * SPAD + m + 8]);
            }
#pragma unroll
            for (int nf = 0; nf < 4; nf++) {
                int n = wn + nf * 8 + g;
                bf[nf][0] = __float_as_uint(Bs[buf][(kk + t) * SPAD + n]);
                bf[nf][1] = __float_as_uint(Bs[buf][(kk + t + 4) * SPAD + n]);
            }
#pragma unroll
            for (int mf = 0; mf < 4; mf++)
#pragma unroll
                for (int nf = 0; nf < 4; nf++) {
                    asm volatile(
                        "mma.sync.aligned.m16n8k8.row.col.f32.tf32.tf32.f32 "
                        "{%0,%1,%2,%3}, {%4,%5,%6,%7}, {%8,%9}, {%0,%1,%2,%3};"
                        : "+f"(acc[mf][nf][0]), "+f"(acc[mf][nf][1]),
                          "+f"(acc[mf][nf][2]), "+f"(acc[mf][nf][3])
                        : "r"(af[mf][0]), "r"(af[mf][1]), "r"(af[mf][2]), "r"(af[mf][3]),
                          "r"(bf[nf][0]), "r"(bf[nf][1]));
                }
        }
        if (kt + 1 < NKT) {
            int nb = buf ^ 1;
            As[nb][ka0 * SPAD + ma0 + 0] = to_tf32(pa0.x); As[nb][ka0 * SPAD + ma0 + 1] = to_tf32(pa0.y);
            As[nb][ka0 * SPAD + ma0 + 2] = to_tf32(pa0.z); As[nb][ka0 * SPAD + ma0 + 3] = to_tf32(pa0.w);
            As[nb][ka1 * SPAD + ma1 + 0] = to_tf32(pa1.x); As[nb][ka1 * SPAD + ma1 + 1] = to_tf32(pa1.y);
            As[nb][ka1 * SPAD + ma1 + 2] = to_tf32(pa1.z); As[nb][ka1 * SPAD + ma1 + 3] = to_tf32(pa1.w);
            *(float4*)&Bs[nb][ka0 * SPAD + ma0] = pb0;
            *(float4*)&Bs[nb][ka1 * SPAD + ma1] = pb1;
        }
        __syncthreads();
    }

    int z = n0 >> 8;
    int ob0 = n0 & 255;
#pragma unroll
    for (int mf = 0; mf < 4; mf++) {
        int m = m0 + wm + mf * 16 + g;
#pragma unroll
        for (int nf = 0; nf < 4; nf++) {
            int o = ob0 + wn + nf * 8 + 2 * t;
            if (m < HW) {
                float* dst = P + ((size_t)z * HW + m) * 256 + o;
                *(float2*)dst = make_float2(acc[mf][nf][0], acc[mf][nf][1]);
            }
            if (m + 8 < HW) {
                float* dst = P + ((size_t)z * HW + m + 8) * 256 + o;
                *(float2*)dst = make_float2(acc[mf][nf][2], acc[mf][nf][3]);
            }
        }
    }
}

// ---------------- merged float4 cumsum of P along w (all levels) ----------------
__global__ void k_prow(void) {
    int t = blockIdx.x * 256 + threadIdx.x;
    if (t >= 107136) return;
    int l = 0;
    while (t >= c_RCUM4[l + 1]) l++;
    int tt = t - c_RCUM4[l];
    int H = c_HH[l], W = c_WW[l];
    int o4 = (tt & 63) * 4;
    int r = tt >> 6;
    int h = r % H, z = r / H;
    float* p = g_P + c_POFF[l] + ((size_t)(z * H + h) * W) * 256 + o4;
    float4 a = make_float4(0, 0, 0, 0);
    for (int w = 0; w < W; w += 4) {
        float4 v0 = *(float4*)(p + (w + 0) * 256);
        float4 v1 = *(float4*)(p + (w + 1) * 256);
        float4 v2 = *(float4*)(p + (w + 2) * 256);
        float4 v3 = *(float4*)(p + (w + 3) * 256);
        a.x += v0.x; a.y += v0.y; a.z += v0.z; a.w += v0.w;
        *(float4*)(p + (w + 0) * 256) = a;
        a.x += v1.x; a.y += v1.y; a.z += v1.z; a.w += v1.w;
        *(float4*)(p + (w + 1) * 256) = a;
        a.x += v2.x; a.y += v2.y; a.z += v2.z; a.w += v2.w;
        *(float4*)(p + (w + 2) * 256) = a;
        a.x += v3.x; a.y += v3.y; a.z += v3.z; a.w += v3.w;
        *(float4*)(p + (w + 3) * 256) = a;
    }
}

// ---------------- merged float4 cumsum of P along h (all levels) ----------------
__global__ void k_pcol(void) {
    int t = blockIdx.x * 256 + threadIdx.x;
    if (t >= 357120) return;
    int l = 0;
    while (t >= c_CCUM4[l + 1]) l++;
    int tt = t - c_CCUM4[l];
    int H = c_HH[l], W = c_WW[l];
    int o4 = (tt & 63) * 4;
    int r = tt >> 6;
    int w = r % W, z = r / W;
    float* p = g_P + c_POFF[l] + ((size_t)z * H * W + w) * 256 + o4;
    int stride = W * 256;
    float4 a = make_float4(0, 0, 0, 0);
    for (int h = 0; h < H; h += 3) {
        float4 v0 = *(float4*)(p + (h + 0) * stride);
        float4 v1 = *(float4*)(p + (h + 1) * stride);
        float4 v2 = *(float4*)(p + (h + 2) * stride);
        a.x += v0.x; a.y += v0.y; a.z += v0.z; a.w += v0.w;
        *(float4*)(p + (h + 0) * stride) = a;
        a.x += v1.x; a.y += v1.y; a.z += v1.z; a.w += v1.w;
        *(float4*)(p + (h + 1) * stride) = a;
        a.x += v2.x; a.y += v2.y; a.z += v2.z; a.w += v2.w;
        *(float4*)(p + (h + 2) * stride) = a;
    }
}

// ---------------- fused gather (dedup-table-driven) ----------------
__global__ __launch_bounds__(256) void k_gather(const float* __restrict__ bias) {
    int n = blockIdx.x;
    int l = blockIdx.y;
    int o = threadIdx.x;
    int Hf = c_HH[l], Wf = c_WW[l];
    int HW = Hf * Wf;
    float areaF = (float)HW * 0.25f;
    const float* __restrict__ P = g_P + c_POFF[l];
    int d = n / NWC;

    const float* ct = g_ctab + (size_t)(l * NCELL + n) * 12;
    float4 cw = *(const float4*)ct;
    int4 co = *(const int4*)(ct + 4);
    float xw = ct[8];
    int ncol = ((const int*)ct)[9];

    float acc = bias[l * 256 + o];

    const float* tab = g_rtab + (size_t)((l * NZ) * ND + d) * 12;
#pragma unroll
    for (int z = 0; z < NZ; z++, tab += ND * 12) {
        float4 rw = *(const float4*)tab;
        int4 ro = *(const int4*)(tab + 4);
        float yh = tab[8];
        int nrow = ((const int*)tab)[9];
        float area = xw * yh * areaF + 1e-6f;
        if (!(area > 1e-6f)) continue;
        float inv = 1.0f / area;
        const float* Pz = P + (size_t)z * HW * 256 + o;

        // row 0
        const float* Pr0 = Pz + ro.x;
        float rs0 = cw.x * Pr0[co.x] + cw.y * Pr0[co.y];
        if (ncol > 2) rs0 += cw.z * Pr0[co.z];
        if (ncol > 3) rs0 += cw.w * Pr0[co.w];
        // row 1
        const float* Pr1 = Pz + ro.y;
        float rs1 = cw.x * Pr1[co.x] + cw.y * Pr1[co.y];
        if (ncol > 2) rs1 += cw.z * Pr1[co.z];
        if (ncol > 3) rs1 += cw.w * Pr1[co.w];
        float s = rw.x * rs0 + rw.y * rs1;
        if (nrow > 2) {
            const float* Pr2 = Pz + ro.z;
            float rs2 = cw.x * Pr2[co.x] + cw.y * Pr2[co.y];
            if (ncol > 2) rs2 += cw.z * Pr2[co.z];
            if (ncol > 3) rs2 += cw.w * Pr2[co.w];
            s += rw.z * rs2;
        }
        if (nrow > 3) {
            const float* Pr3 = Pz + ro.w;
            float rs3 = cw.x * Pr3[co.x] + cw.y * Pr3[co.y];
            if (ncol > 2) rs3 += cw.z * Pr3[co.z];
            if (ncol > 3) rs3 += cw.w * Pr3[co.w];
            s += rw.w * rs3;
        }
        acc += inv * s;
    }
    int w = n - d * NWC;
    int sp = w * ND + d;
    g_xcat[(l * 256 + o) * NCELL + sp] = fmaxf(acc, 0.0f);
}

// ---------------- channel means ----------------
__global__ void k_colmean() {
    int g = blockIdx.x;
    const float* p = g_xcat + g * NCELL;
    float s = 0.f;
    for (int i = threadIdx.x; i < NCELL; i += 256) s += p[i];
    __shared__ float sm[256];
    sm[threadIdx.x] = s;
    __syncthreads();
    for (int st = 128; st > 0; st >>= 1) {
        if (threadIdx.x < st) sm[threadIdx.x] += sm[threadIdx.x + st];
        __syncthreads();
    }
    if (threadIdx.x == 0) g_colmean[g] = sm[0] * (1.0f / (float)NCELL);
}

__global__ void k_att(const float* __restrict__ aw, const float* __restrict__ ab) {
    __shared__ float cm[IMC_];
    int l = blockIdx.x, o = threadIdx.x;
    cm[o] = g_colmean[l * IMC_ + o];
    __syncthreads();
    float acc = ab[o];
    for (int c = 0; c < IMC_; c++) acc += cm[c] * aw[o * IMC_ + c];
    g_sig[l * IMC_ + o] = 1.0f / (1.0f + expf(-acc));
}

// ---------------- fold attention + transpose conv1 weights -> tf32 [k][o] ----------------
__global__ void k_wscale(const float* __restrict__ w) {
    int idx = blockIdx.x * 256 + threadIdx.x;
    if (idx >= CATC * 9 * IMC_) return;
    int o = idx & 255;
    int t = idx >> 8;
    int kk = t % 9;
    int cin = t / 9;
    g_w1s[idx] = to_tf32(w[(o * CATC + cin) * 9 + kk] * g_sig[cin]);
}

__global__ void k_permw2(const float* __restrict__ w) {
    int idx = blockIdx.x * 256 + threadIdx.x;
    if (idx >= IMC_ * 9 * IMC_) return;
    int o = idx & 255;
    int t = idx >> 8;
    int kk = t % 9;
    int cin = t / 9;
    g_w2p[idx] = to_tf32(w[(o * IMC_ + cin) * 9 + kk]);
}

// ---------------- implicit-GEMM tf32 conv (3x3, pad 1), split-K partials ----------------
#define APAD 68
#define BPAD 132
template<int STRIDE, int IH, int IW, int CONV1, int KCHUNK>
__global__ __launch_bounds__(256) void k_convmma() {
    const float* __restrict__ src = CONV1 ? g_xcat : g_y1;
    const float* __restrict__ wt  = CONV1 ? g_w1s : g_w2p;
    float* __restrict__ part = (CONV1 ? g_c1part : g_c2part) + (size_t)blockIdx.z * IMC_ * OSP;

    __shared__ float As[2][16 * APAD];
    __shared__ float Bs[2][16 * BPAD];

    int tid = threadIdx.x;
    int m0 = blockIdx.x * 64;
    int n0 = blockIdx.y * 128;
    int kbase = blockIdx.z * KCHUNK;

    int lane = tid & 31;
    int g = lane >> 2, t4 = lane & 3;
    int wid = tid >> 5;
    int wm = (wid & 1) * 32;
    int wn = (wid >> 1) * 32;

    int ma = tid & 63;
    int kqa = tid >> 6;
    int m = m0 + ma;
    bool mv = m < OSP;
    int mq = mv ? m : 0;
    int oh = mq / OW1, ow = mq - oh * OW1;
    int ihb = STRIDE * oh - 1, iwb = STRIDE * ow - 1;

    int nb = (tid & 31) * 4;
    int kqb = tid >> 5;

    float acc[2][4][4];
#pragma unroll
    for (int i = 0; i < 2; i++)
#pragma unroll
        for (int j = 0; j < 4; j++)
#pragma unroll
            for (int q = 0; q < 4; q++) acc[i][j][q] = 0.f;

    {
#pragma unroll
        for (int i = 0; i < 4; i++) {
            int kg = kbase + kqa * 4 + i;
            int cin = kg / 9; int r = kg - cin * 9;
            int ky = r / 3, kx = r - ky * 3;
            int ih = ihb + ky, iw = iwb + kx;
            bool ok = mv && ih >= 0 && ih < IH && iw >= 0 && iw < IW;
            float v = ok ? src[(size_t)cin * (IH * IW) + ih * IW + iw] : 0.f;
            As[0][(kqa * 4 + i) * APAD + ma] = to_tf32(v);
        }
#pragma unroll
        for (int p = 0; p < 2; p++) {
            int kk = kqb + p * 8;
            *(float4*)&Bs[0][kk * BPAD + nb] = *(const float4*)(wt + (size_t)(kbase + kk) * 256 + n0 + nb);
        }
    }
    __syncthreads();

    const int NT = KCHUNK / 16;
    for (int kt = 0; kt < NT; kt++) {
        int buf = kt & 1;
        float pa[4];
        float4 pb[2];
        if (kt + 1 < NT) {
            int k0n = kbase + (kt + 1) * 16;
#pragma unroll
            for (int i = 0; i < 4; i++) {
                int kg = k0n + kqa * 4 + i;
                int cin = kg / 9; int r = kg - cin * 9;
                int ky = r / 3, kx = r - ky * 3;
                int ih = ihb + ky, iw = iwb + kx;
                bool ok = mv && ih >= 0 && ih < IH && iw >= 0 && iw < IW;
                pa[i] = ok ? src[(size_t)cin * (IH * IW) + ih * IW + iw] : 0.f;
            }
#pragma unroll
            for (int p = 0; p < 2; p++) {
                int kk = kqb + p * 8;
                pb[p] = *(const float4*)(wt + (size_t)(k0n + kk) * 256 + n0 + nb);
            }
        }
#pragma unroll
        for (int ks = 0; ks < 2; ks++) {
            int kk = ks * 8;
            uint32_t af[2][4], bf[4][2];
#pragma unroll
            for (int mf = 0; mf < 2; mf++) {
                int mm = wm + mf * 16 + g;
                af[mf][0] = __float_as_uint(As[buf][(kk + t4) * APAD + mm]);
                af[mf][1] = __float_as_uint(As[buf][(kk + t4) * APAD + mm + 8]);
                af[mf][2] = __float_as_uint(As[buf][(kk + t4 + 4) * APAD + mm]);
                af[mf][3] = __float_as_uint(As[buf][(kk + t4 + 4) * APAD + mm + 8]);
            }
#pragma unroll
            for (int nf = 0; nf < 4; nf++) {
                int nn = wn + nf * 8 + g;
                bf[nf][0] = __float_as_uint(Bs[buf][(kk + t4) * BPAD + nn]);
                bf[nf][1] = __float_as_uint(Bs[buf][(kk + t4 + 4) * BPAD + nn]);
            }
#pragma unroll
            for (int mf = 0; mf < 2; mf++)
#pragma unroll
                for (int nf = 0; nf < 4; nf++) {
                    asm volatile(
                        "mma.sync.aligned.m16n8k8.row.col.f32.tf32.tf32.f32 "
                        "{%0,%1,%2,%3}, {%4,%5,%6,%7}, {%8,%9}, {%0,%1,%2,%3};"
                        : "+f"(acc[mf][nf][0]), "+f"(acc[mf][nf][1]),
                          "+f"(acc[mf][nf][2]), "+f"(acc[mf][nf][3])
                        : "r"(af[mf][0]), "r"(af[mf][1]), "r"(af[mf][2]), "r"(af[mf][3]),
                          "r"(bf[nf][0]), "r"(bf[nf][1]));
                }
        }
        if (kt + 1 < NT) {
            int b2 = buf ^ 1;
#pragma unroll
            for (int i = 0; i < 4; i++)
                As[b2][(kqa * 4 + i) * APAD + ma] = to_tf32(pa[i]);
#pragma unroll
            for (int p = 0; p < 2; p++)
                *(float4*)&Bs[b2][(kqb + p * 8) * BPAD + nb] = pb[p];
        }
        __syncthreads();
    }

#pragma unroll
    for (int mf = 0; mf < 2; mf++) {
        int mrow = m0 + wm + mf * 16 + g;
#pragma unroll
        for (int nf = 0; nf < 4; nf++) {
            int o = n0 + wn + nf * 8 + 2 * t4;
            if (mrow < OSP) {
                part[(size_t)o * OSP + mrow] = acc[mf][nf][0];
                part[(size_t)(o + 1) * OSP + mrow] = acc[mf][nf][1];
            }
            if (mrow + 8 < OSP) {
                part[(size_t)o * OSP + mrow + 8] = acc[mf][nf][2];
                part[(size_t)(o + 1) * OSP + mrow + 8] = acc[mf][nf][3];
            }
        }
    }
}

__global__ void k_c1red(const float* __restrict__ bg, const float* __restrict__ bb,
                        const float* __restrict__ bm, const float* __restrict__ bv) {
    int idx = blockIdx.x * 256 + threadIdx.x;
    if (idx >= IMC_ * OSP) return;
    int o = idx / OSP;
    float s = g_c1part[idx] + g_c1part[IMC_ * OSP + idx]
            + g_c1part[2 * IMC_ * OSP + idx] + g_c1part[3 * IMC_ * OSP + idx];
    float sc = bg[o] / sqrtf(bv[o] + 1e-5f);
    g_y1[idx] = fmaxf((s - bm[o]) * sc + bb[o], 0.f);
}

__global__ void k_c2red(const float* __restrict__ bg, const float* __restrict__ bb,
                        const float* __restrict__ bm, const float* __restrict__ bv,
                        float* __restrict__ out) {
    int idx = blockIdx.x * 256 + threadIdx.x;
    if (idx >= IMC_ * OSP) return;
    int o = idx / OSP;
    float s = g_c2part[idx] + g_c2part[IMC_ * OSP + idx];
    float sc = bg[o] / sqrtf(bv[o] + 1e-5f);
    out[idx] = fmaxf((s - bm[o]) * sc + bb[o], 0.f);
}

// ---------------- launch ----------------
extern "C" void kernel_launch(void* const* d_in, const int* in_sizes, int n_in,
                              void* d_out, int out_size) {
    (void)in_sizes; (void)n_in; (void)out_size;
    const float* f0 = (const float*)d_in[0];
    const float* f1 = (const float*)d_in[1];
    const float* f2 = (const float*)d_in[2];
    const float* f3 = (const float*)d_in[3];
    const float* f4 = (const float*)d_in[4];
    const float* calib = (const float*)d_in[5];
    const float* oftw  = (const float*)d_in[6];
    const float* oftb  = (const float*)d_in[7];
    const float* attw  = (const float*)d_in[8];
    const float* attb  = (const float*)d_in[9];
    const float* c1w   = (const float*)d_in[10];
    const float* b1g   = (const float*)d_in[11];
    const float* b1b   = (const float*)d_in[12];
    const float* b1m   = (const float*)d_in[13];
    const float* b1v   = (const float*)d_in[14];
    const float* c2w   = (const float*)d_in[15];
    const float* b2g   = (const float*)d_in[16];
    const float* b2b   = (const float*)d_in[17];
    const float* b2m   = (const float*)d_in[18];
    const float* b2v   = (const float*)d_in[19];
    float* out = (float*)d_out;

    k_ctab<<<(5 * NCELL + 255) / 256, 256>>>(calib);
    k_rtab<<<(5 * NZ * ND + 255) / 256, 256>>>(calib);
    k_permwb<<<(5 * 256 * HC_ + 255) / 256, 256>>>(oftw);
    k_permw2<<<(IMC_ * 9 * IMC_ + 255) / 256, 256>>>(c2w);

    k_pgemm<<<dim3(320, 18), 256>>>(f0, f1, f2, f3, f4);

    k_prow<<<(107136 + 255) / 256, 256>>>();
    k_pcol<<<(357120 + 255) / 256, 256>>>();
    k_gather<<<dim3(NCELL, 5), 256>>>(oftb);

    k_colmean<<<CATC, 256>>>();
    k_att<<<5, 256>>>(attw, attb);
    k_wscale<<<(CATC * 9 * IMC_ + 255) / 256, 256>>>(c1w);

    // conv1: K = 1280*9 = 11520, split-K 4 (chunk 2880)
    k_convmma<2, NWC, ND, 1, 2880><<<dim3((OSP + 63) / 64, 2, 4), 256>>>();
    k_c1red<<<(IMC_ * OSP + 255) / 256, 256>>>(b1g, b1b, b1m, b1v);
    // conv2: K = 256*9 = 2304, split-K 2 (chunk 1152)
    k_convmma<1, OH1, OW1, 0, 1152><<<dim3((OSP + 63) / 64, 2, 2), 256>>>();
    k_c2red<<<(IMC_ * OSP + 255) / 256, 256>>>(b2g, b2b, b2m, b2v, out);
}